// round 1
// baseline (speedup 1.0000x reference)
#include <cuda_runtime.h>

// ---------------------------------------------------------------------------
// Problem constants
// ---------------------------------------------------------------------------
#define NTOK   16384      // B*S
#define DMODEL 1024
#define NH     16
#define DH     64
#define SEGLEN 64
#define NSEG   64
#define SLEN   4096
#define NBATCH 4
#define NEGINF -1e10f

// ---------------------------------------------------------------------------
// Scratch (device globals: allocation-free per harness rules)
// ---------------------------------------------------------------------------
__device__ float g_q [NTOK * DMODEL];
__device__ float g_k [NTOK * DMODEL];
__device__ float g_v [NTOK * DMODEL];
__device__ float g_ra[NTOK * DMODEL];   // row_attn (unmasked local softmax @ V)
__device__ float g_la[NTOK * DMODEL];   // unnormalized masked-local P@V
__device__ float g_kt[NTOK * DMODEL];   // key_row tmp (Wrow_out + residual, LN in place)
__device__ float g_k2[NTOK * DMODEL];   // key_row2 (post Wk2)
__device__ float g_mg[NTOK * DMODEL];   // merged
__device__ float g_mloc[NTOK * NH];     // masked-local row max
__device__ float g_sloc[NTOK * NH];     // masked-local row sumexp

// ---------------------------------------------------------------------------
// SGEMM: C = alpha * (A[MxK] @ B[KxN]) (+ res)   row-major, M%128==N%128==K%8==0
// ---------------------------------------------------------------------------
#define BM 128
#define BN 128
#define BK 8
#define TM 8
#define TN 8

__global__ __launch_bounds__(256) void sgemm_k(
    const float* __restrict__ A, const float* __restrict__ Bm,
    const float* __restrict__ res, float* __restrict__ C,
    int M, int N, int K, float alpha)
{
    __shared__ float As[BK][BM];
    __shared__ float Bs[BK][BN];

    const int cRow = blockIdx.y;
    const int cCol = blockIdx.x;
    const int tid  = threadIdx.x;

    const int threadCol = tid & 15;   // 0..15
    const int threadRow = tid >> 4;   // 0..15

    const int aRow = tid >> 1;          // 0..127
    const int aCol = (tid & 1) << 2;    // 0 or 4
    const int bRow = tid >> 5;          // 0..7
    const int bCol = (tid & 31) << 2;   // 0..124

    const float* Ab = A + (size_t)cRow * BM * K;
    const float* Bb = Bm + cCol * BN;

    float acc[TM][TN];
    #pragma unroll
    for (int i = 0; i < TM; i++)
        #pragma unroll
        for (int j = 0; j < TN; j++) acc[i][j] = 0.0f;

    for (int k0 = 0; k0 < K; k0 += BK) {
        float4 a4 = *(const float4*)(Ab + (size_t)aRow * K + k0 + aCol);
        As[aCol + 0][aRow] = a4.x;
        As[aCol + 1][aRow] = a4.y;
        As[aCol + 2][aRow] = a4.z;
        As[aCol + 3][aRow] = a4.w;
        float4 b4 = *(const float4*)(Bb + (size_t)(k0 + bRow) * N + bCol);
        *(float4*)&Bs[bRow][bCol] = b4;
        __syncthreads();

        #pragma unroll
        for (int kk = 0; kk < BK; kk++) {
            float4 a0 = *(const float4*)(&As[kk][threadRow * TM]);
            float4 a1 = *(const float4*)(&As[kk][threadRow * TM + 4]);
            float4 b0 = *(const float4*)(&Bs[kk][threadCol * TN]);
            float4 b1 = *(const float4*)(&Bs[kk][threadCol * TN + 4]);
            float ar[TM] = {a0.x, a0.y, a0.z, a0.w, a1.x, a1.y, a1.z, a1.w};
            float br[TN] = {b0.x, b0.y, b0.z, b0.w, b1.x, b1.y, b1.z, b1.w};
            #pragma unroll
            for (int i = 0; i < TM; i++)
                #pragma unroll
                for (int j = 0; j < TN; j++)
                    acc[i][j] += ar[i] * br[j];
        }
        __syncthreads();
    }

    #pragma unroll
    for (int i = 0; i < TM; i++) {
        size_t r = (size_t)(cRow * BM + threadRow * TM + i);
        int cbase = cCol * BN + threadCol * TN;
        #pragma unroll
        for (int j = 0; j < TN; j += 4) {
            float4 o;
            o.x = alpha * acc[i][j + 0];
            o.y = alpha * acc[i][j + 1];
            o.z = alpha * acc[i][j + 2];
            o.w = alpha * acc[i][j + 3];
            if (res) {
                float4 rr = *(const float4*)(res + r * N + cbase + j);
                o.x += rr.x; o.y += rr.y; o.z += rr.z; o.w += rr.w;
            }
            *(float4*)(C + r * N + cbase + j) = o;
        }
    }
}

// ---------------------------------------------------------------------------
// Warp utils
// ---------------------------------------------------------------------------
__device__ __forceinline__ float warp_max(float v) {
    #pragma unroll
    for (int o = 16; o > 0; o >>= 1) v = fmaxf(v, __shfl_xor_sync(0xffffffffu, v, o));
    return v;
}
__device__ __forceinline__ float warp_sum(float v) {
    #pragma unroll
    for (int o = 16; o > 0; o >>= 1) v += __shfl_xor_sync(0xffffffffu, v, o);
    return v;
}

#define PCH 65  // smem pitch (64 + 1 pad)

// ---------------------------------------------------------------------------
// Local attention: one block per (b, seg, h).
// Computes: logits = q@k^T (64x64)
//   unmasked softmax -> row_attn = P@V                 (-> g_ra)
//   causal-masked stats m,s and unnormalized Pm@V      (-> g_mloc,g_sloc,g_la)
// ---------------------------------------------------------------------------
__global__ __launch_bounds__(256) void attn_local_k()
{
    extern __shared__ float sm[];
    float* sq = sm;
    float* sk = sm + 64 * PCH;
    float* sv = sm + 2 * 64 * PCH;

    int bid = blockIdx.x;
    int h   = bid % NH;
    int seg = (bid / NH) % NSEG;
    int b   = bid / (NH * NSEG);
    int t0  = b * SLEN + seg * SEGLEN;
    int tid = threadIdx.x;

    for (int idx = tid; idx < 1024; idx += 256) {
        int r = idx >> 4;
        int c = (idx & 15) << 2;
        size_t g = (size_t)(t0 + r) * DMODEL + h * DH + c;
        float4 a = *(const float4*)(g_q + g);
        sq[r * PCH + c] = a.x; sq[r * PCH + c + 1] = a.y;
        sq[r * PCH + c + 2] = a.z; sq[r * PCH + c + 3] = a.w;
        float4 bb = *(const float4*)(g_k + g);
        sk[r * PCH + c] = bb.x; sk[r * PCH + c + 1] = bb.y;
        sk[r * PCH + c + 2] = bb.z; sk[r * PCH + c + 3] = bb.w;
        float4 vv = *(const float4*)(g_v + g);
        sv[r * PCH + c] = vv.x; sv[r * PCH + c + 1] = vv.y;
        sv[r * PCH + c + 2] = vv.z; sv[r * PCH + c + 3] = vv.w;
    }
    __syncthreads();

    int tx = tid & 15, ty = tid >> 4;
    float acc[4][4];
    #pragma unroll
    for (int i = 0; i < 4; i++)
        #pragma unroll
        for (int j = 0; j < 4; j++) acc[i][j] = 0.0f;

    for (int d = 0; d < 64; d++) {
        float qa[4], kb[4];
        #pragma unroll
        for (int i = 0; i < 4; i++) qa[i] = sq[(ty * 4 + i) * PCH + d];
        #pragma unroll
        for (int j = 0; j < 4; j++) kb[j] = sk[(tx * 4 + j) * PCH + d];
        #pragma unroll
        for (int i = 0; i < 4; i++)
            #pragma unroll
            for (int j = 0; j < 4; j++) acc[i][j] += qa[i] * kb[j];
    }
    __syncthreads();   // all reads of sq/sk done

    #pragma unroll
    for (int i = 0; i < 4; i++)
        #pragma unroll
        for (int j = 0; j < 4; j++)
            sq[(ty * 4 + i) * PCH + tx * 4 + j] = acc[i][j];  // raw logits -> sq
    __syncthreads();

    int warp = tid >> 5, lane = tid & 31;
    for (int r = warp; r < 64; r += 8) {
        float l0 = sq[r * PCH + lane];
        float l1 = sq[r * PCH + 32 + lane];
        float mx = warp_max(fmaxf(l0, l1));                    // unmasked max
        float k0 = (lane <= r)      ? l0 : -3e38f;
        float k1 = (lane + 32 <= r) ? l1 : -3e38f;
        float mm = warp_max(fmaxf(k0, k1));                    // masked max
        float e0 = __expf(l0 - mx), e1 = __expf(l1 - mx);
        float su = warp_sum(e0 + e1);
        float em0 = (lane <= r)      ? __expf(l0 - mm) : 0.0f;
        float em1 = (lane + 32 <= r) ? __expf(l1 - mm) : 0.0f;
        float ss = warp_sum(em0 + em1);
        float inv = 1.0f / su;
        sq[r * PCH + lane]      = e0 * inv;   // normalized unmasked probs
        sq[r * PCH + 32 + lane] = e1 * inv;
        sk[r * PCH + lane]      = em0;        // unnormalized masked exp
        sk[r * PCH + 32 + lane] = em1;
        if (lane == 0) {
            g_mloc[(t0 + r) * NH + h] = mm;
            g_sloc[(t0 + r) * NH + h] = ss;
        }
    }
    __syncthreads();

    float a1[4][4], a2[4][4];
    #pragma unroll
    for (int i = 0; i < 4; i++)
        #pragma unroll
        for (int j = 0; j < 4; j++) { a1[i][j] = 0.0f; a2[i][j] = 0.0f; }

    for (int j = 0; j < 64; j++) {
        float vv[4];
        #pragma unroll
        for (int jj = 0; jj < 4; jj++) vv[jj] = sv[j * PCH + tx * 4 + jj];
        #pragma unroll
        for (int ii = 0; ii < 4; ii++) {
            float pu = sq[(ty * 4 + ii) * PCH + j];
            float pm = sk[(ty * 4 + ii) * PCH + j];
            #pragma unroll
            for (int jj = 0; jj < 4; jj++) {
                a1[ii][jj] += pu * vv[jj];
                a2[ii][jj] += pm * vv[jj];
            }
        }
    }

    #pragma unroll
    for (int ii = 0; ii < 4; ii++) {
        size_t base = (size_t)(t0 + ty * 4 + ii) * DMODEL + h * DH + tx * 4;
        float4 o1 = {a1[ii][0], a1[ii][1], a1[ii][2], a1[ii][3]};
        float4 o2 = {a2[ii][0], a2[ii][1], a2[ii][2], a2[ii][3]};
        *(float4*)(g_ra + base) = o1;
        *(float4*)(g_la + base) = o2;
    }
}

// ---------------------------------------------------------------------------
// Global attention + merge: one block per (b, l, h).
// glog[qs][ks] = q[b,qs,l,h,:] . key2[b,ks,l,h,:] + (ks>=qs ? NEG : 0)
// merged = (local_acc*e^{m_loc-m} + glob_acc*e^{m_g-m}) / (s_loc e^.. + s_g e^..)
// ---------------------------------------------------------------------------
__global__ __launch_bounds__(256) void attn_global_k()
{
    extern __shared__ float sm[];
    float* sq = sm;
    float* sk = sm + 64 * PCH;
    float* sr = sm + 2 * 64 * PCH;
    __shared__ float s_cl[64], s_cg[64];

    int bid = blockIdx.x;
    int h   = bid % NH;
    int l   = (bid / NH) % SEGLEN;
    int b   = bid / (NH * SEGLEN);
    int tid = threadIdx.x;

    for (int idx = tid; idx < 1024; idx += 256) {
        int r = idx >> 4;
        int c = (idx & 15) << 2;
        size_t g = (size_t)(b * SLEN + r * SEGLEN + l) * DMODEL + h * DH + c;
        float4 a = *(const float4*)(g_q + g);
        sq[r * PCH + c] = a.x; sq[r * PCH + c + 1] = a.y;
        sq[r * PCH + c + 2] = a.z; sq[r * PCH + c + 3] = a.w;
        float4 kk = *(const float4*)(g_k2 + g);
        sk[r * PCH + c] = kk.x; sk[r * PCH + c + 1] = kk.y;
        sk[r * PCH + c + 2] = kk.z; sk[r * PCH + c + 3] = kk.w;
        float4 rr = *(const float4*)(g_ra + g);
        sr[r * PCH + c] = rr.x; sr[r * PCH + c + 1] = rr.y;
        sr[r * PCH + c + 2] = rr.z; sr[r * PCH + c + 3] = rr.w;
    }
    __syncthreads();

    int tx = tid & 15, ty = tid >> 4;
    float acc[4][4];
    #pragma unroll
    for (int i = 0; i < 4; i++)
        #pragma unroll
        for (int j = 0; j < 4; j++) acc[i][j] = 0.0f;

    for (int d = 0; d < 64; d++) {
        float qa[4], kb[4];
        #pragma unroll
        for (int i = 0; i < 4; i++) qa[i] = sq[(ty * 4 + i) * PCH + d];
        #pragma unroll
        for (int j = 0; j < 4; j++) kb[j] = sk[(tx * 4 + j) * PCH + d];
        #pragma unroll
        for (int i = 0; i < 4; i++)
            #pragma unroll
            for (int j = 0; j < 4; j++) acc[i][j] += qa[i] * kb[j];
    }
    __syncthreads();

    #pragma unroll
    for (int ii = 0; ii < 4; ii++)
        #pragma unroll
        for (int jj = 0; jj < 4; jj++) {
            int i = ty * 4 + ii, j = tx * 4 + jj;
            sq[i * PCH + j] = acc[ii][jj] + ((j >= i) ? NEGINF : 0.0f);
        }
    __syncthreads();

    int warp = tid >> 5, lane = tid & 31;
    for (int r = warp; r < 64; r += 8) {
        float l0 = sq[r * PCH + lane];
        float l1 = sq[r * PCH + 32 + lane];
        float mg = warp_max(fmaxf(l0, l1));
        float e0 = __expf(l0 - mg), e1 = __expf(l1 - mg);
        float sg = warp_sum(e0 + e1);
        sq[r * PCH + lane]      = e0;   // unnormalized global exp
        sq[r * PCH + 32 + lane] = e1;
        if (lane == 0) {
            int t = b * SLEN + r * SEGLEN + l;
            float mlc = g_mloc[t * NH + h];
            float slc = g_sloc[t * NH + h];
            float m  = fmaxf(mlc, mg);
            float al = __expf(mlc - m);
            float ag = __expf(mg - m);
            float inv = 1.0f / (slc * al + sg * ag);
            s_cl[r] = al * inv;
            s_cg[r] = ag * inv;
        }
    }
    __syncthreads();

    float ga[4][4];
    #pragma unroll
    for (int i = 0; i < 4; i++)
        #pragma unroll
        for (int j = 0; j < 4; j++) ga[i][j] = 0.0f;

    for (int j = 0; j < 64; j++) {
        float rv[4];
        #pragma unroll
        for (int jj = 0; jj < 4; jj++) rv[jj] = sr[j * PCH + tx * 4 + jj];
        #pragma unroll
        for (int ii = 0; ii < 4; ii++) {
            float p = sq[(ty * 4 + ii) * PCH + j];
            #pragma unroll
            for (int jj = 0; jj < 4; jj++) ga[ii][jj] += p * rv[jj];
        }
    }

    #pragma unroll
    for (int ii = 0; ii < 4; ii++) {
        int i = ty * 4 + ii;
        size_t base = (size_t)(b * SLEN + i * SEGLEN + l) * DMODEL + h * DH + tx * 4;
        float4 la = *(const float4*)(g_la + base);
        float cl = s_cl[i], cg = s_cg[i];
        float4 o;
        o.x = cl * la.x + cg * ga[ii][0];
        o.y = cl * la.y + cg * ga[ii][1];
        o.z = cl * la.z + cg * ga[ii][2];
        o.w = cl * la.w + cg * ga[ii][3];
        *(float4*)(g_mg + base) = o;
    }
}

// ---------------------------------------------------------------------------
// LayerNorm (in place): one block per token row of 1024
// ---------------------------------------------------------------------------
__global__ __launch_bounds__(256) void ln_k(float* __restrict__ x,
                                            const float* __restrict__ sc,
                                            const float* __restrict__ bs)
{
    size_t row = blockIdx.x;
    float* p = x + row * DMODEL;
    int c = threadIdx.x * 4;
    float4 v = *(float4*)(p + c);
    float s  = v.x + v.y + v.z + v.w;
    float sq = v.x * v.x + v.y * v.y + v.z * v.z + v.w * v.w;
    s  = warp_sum(s);
    sq = warp_sum(sq);
    __shared__ float rs[8], rq[8];
    int warp = threadIdx.x >> 5, lane = threadIdx.x & 31;
    if (lane == 0) { rs[warp] = s; rq[warp] = sq; }
    __syncthreads();
    if (warp == 0) {
        float a = (lane < 8) ? rs[lane] : 0.0f;
        float b = (lane < 8) ? rq[lane] : 0.0f;
        a = warp_sum(a);
        b = warp_sum(b);
        if (lane == 0) { rs[0] = a; rq[0] = b; }
    }
    __syncthreads();
    float mean = rs[0] * (1.0f / DMODEL);
    float var  = rq[0] * (1.0f / DMODEL) - mean * mean;
    float inv  = rsqrtf(var + 1e-6f);
    float4 g = *(const float4*)(sc + c);
    float4 b4 = *(const float4*)(bs + c);
    v.x = (v.x - mean) * inv * g.x + b4.x;
    v.y = (v.y - mean) * inv * g.y + b4.y;
    v.z = (v.z - mean) * inv * g.z + b4.z;
    v.w = (v.w - mean) * inv * g.w + b4.w;
    *(float4*)(p + c) = v;
}

// ---------------------------------------------------------------------------
// Host launcher
// ---------------------------------------------------------------------------
extern "C" void kernel_launch(void* const* d_in, const int* in_sizes, int n_in,
                              void* d_out, int out_size)
{
    const float* x    = (const float*)d_in[0];
    const float* Wq   = (const float*)d_in[1];
    const float* Wk   = (const float*)d_in[2];
    const float* Wv   = (const float*)d_in[3];
    const float* Wrow = (const float*)d_in[4];
    const float* lns  = (const float*)d_in[5];
    const float* lnb  = (const float*)d_in[6];
    const float* Wk2  = (const float*)d_in[7];
    const float* Wout = (const float*)d_in[8];
    float* out = (float*)d_out;

    float *q, *k, *v, *ra, *la, *kt, *k2, *mg;
    cudaGetSymbolAddress((void**)&q,  g_q);
    cudaGetSymbolAddress((void**)&k,  g_k);
    cudaGetSymbolAddress((void**)&v,  g_v);
    cudaGetSymbolAddress((void**)&ra, g_ra);
    cudaGetSymbolAddress((void**)&la, g_la);
    cudaGetSymbolAddress((void**)&kt, g_kt);
    cudaGetSymbolAddress((void**)&k2, g_k2);
    cudaGetSymbolAddress((void**)&mg, g_mg);

    const int ATT_SMEM = 3 * 64 * PCH * (int)sizeof(float);  // 49,920 B
    cudaFuncSetAttribute(attn_local_k,  cudaFuncAttributeMaxDynamicSharedMemorySize, ATT_SMEM);
    cudaFuncSetAttribute(attn_global_k, cudaFuncAttributeMaxDynamicSharedMemorySize, ATT_SMEM);

    dim3 gg(DMODEL / BN, NTOK / BM);
    dim3 bt(256);

    // q/k/v projections (q scaled by 1/sqrt(HD) = 0.125)
    sgemm_k<<<gg, bt>>>(x, Wq, nullptr, q, NTOK, DMODEL, DMODEL, 0.125f);
    sgemm_k<<<gg, bt>>>(x, Wk, nullptr, k, NTOK, DMODEL, DMODEL, 1.0f);
    sgemm_k<<<gg, bt>>>(x, Wv, nullptr, v, NTOK, DMODEL, DMODEL, 1.0f);

    // local attention: row_attn + masked-local stats
    attn_local_k<<<NBATCH * NSEG * NH, 256, ATT_SMEM>>>();

    // key_row = row_attn @ Wrow_out + x ; LayerNorm ; @ Wk2
    sgemm_k<<<gg, bt>>>(ra, Wrow, x, kt, NTOK, DMODEL, DMODEL, 1.0f);
    ln_k<<<NTOK, 256>>>(kt, lns, lnb);
    sgemm_k<<<gg, bt>>>(kt, Wk2, nullptr, k2, NTOK, DMODEL, DMODEL, 1.0f);

    // global attention + softmax merge -> merged
    attn_global_k<<<NBATCH * SEGLEN * NH, 256, ATT_SMEM>>>();

    // output projection
    sgemm_k<<<gg, bt>>>(mg, Wout, nullptr, out, NTOK, DMODEL, DMODEL, 1.0f);
}

// round 3
// speedup vs baseline: 2.2967x; 2.2967x over previous
#include <cuda_runtime.h>
#include <cuda_bf16.h>
#include <cstdint>

// ---------------------------------------------------------------------------
// Problem constants
// ---------------------------------------------------------------------------
#define NTOK   16384      // B*S
#define DMODEL 1024
#define NH     16
#define DH     64
#define SEGLEN 64
#define NSEG   64
#define SLEN   4096
#define NBATCH 4
#define NEGINF -1e10f

// ---------------------------------------------------------------------------
// Scratch (device globals)
// ---------------------------------------------------------------------------
__device__ float g_q [NTOK * DMODEL];
__device__ float g_k [NTOK * DMODEL];
__device__ float g_v [NTOK * DMODEL];
__device__ float g_ra[NTOK * DMODEL];
__device__ float g_la[NTOK * DMODEL];
__device__ float g_kt[NTOK * DMODEL];
__device__ float g_k2[NTOK * DMODEL];
__device__ float g_mg[NTOK * DMODEL];
__device__ float g_mloc[NTOK * NH];
__device__ float g_sloc[NTOK * NH];

// Pre-transposed + bf16-split weights: [6][N=1024][K=1024]
__device__ __nv_bfloat16 g_wh[6][DMODEL * DMODEL];
__device__ __nv_bfloat16 g_wl[6][DMODEL * DMODEL];
// Activation bf16 hi/lo (reused across GEMMs)
__device__ __nv_bfloat16 g_ah[NTOK * DMODEL];
__device__ __nv_bfloat16 g_al[NTOK * DMODEL];

// ---------------------------------------------------------------------------
// Helpers
// ---------------------------------------------------------------------------
__device__ __forceinline__ uint32_t smem_u32(const void* p) {
    uint32_t a;
    asm("{ .reg .u64 t; cvta.to.shared.u64 t, %1; cvt.u32.u64 %0, t; }"
        : "=r"(a) : "l"(p));
    return a;
}
__device__ __forceinline__ void cpasync16(uint32_t s, const void* g) {
    asm volatile("cp.async.cg.shared.global [%0], [%1], 16;" :: "r"(s), "l"(g));
}
#define CP_COMMIT() asm volatile("cp.async.commit_group;")
#define CP_WAIT1()  asm volatile("cp.async.wait_group 1;")
#define CP_WAIT0()  asm volatile("cp.async.wait_group 0;")

#define LDSM4(r0, r1, r2, r3, addr) \
    asm volatile("ldmatrix.sync.aligned.m8n8.x4.shared.b16 {%0,%1,%2,%3}, [%4];" \
                 : "=r"(r0), "=r"(r1), "=r"(r2), "=r"(r3) : "r"(addr))

#define MMA16816(c0, c1, c2, c3, a0, a1, a2, a3, b0, b1) \
    asm volatile("mma.sync.aligned.m16n8k16.row.col.f32.bf16.bf16.f32 " \
                 "{%0,%1,%2,%3}, {%4,%5,%6,%7}, {%8,%9}, {%0,%1,%2,%3};" \
                 : "+f"(c0), "+f"(c1), "+f"(c2), "+f"(c3) \
                 : "r"(a0), "r"(a1), "r"(a2), "r"(a3), "r"(b0), "r"(b1))

__device__ __forceinline__ uint32_t f2bf_bits(float v) {
    return (uint32_t)__bfloat16_as_ushort(__float2bfloat16(v));
}
__device__ __forceinline__ float bf_bits2f(uint32_t b) {
    return __uint_as_float(b << 16);
}

// ---------------------------------------------------------------------------
// Weight transpose + bf16 hi/lo split:  W[K][N] -> Th/Tl[N][K]
// ---------------------------------------------------------------------------
__global__ __launch_bounds__(256) void wsplit_k(const float* __restrict__ W,
                                                __nv_bfloat16* __restrict__ Th,
                                                __nv_bfloat16* __restrict__ Tl)
{
    __shared__ float t[32][33];
    int bn = blockIdx.x * 32;
    int bk = blockIdx.y * 32;
    int x = threadIdx.x & 31;
    int y = threadIdx.x >> 5;
    #pragma unroll
    for (int i = 0; i < 32; i += 8)
        t[y + i][x] = W[(size_t)(bk + y + i) * DMODEL + bn + x];
    __syncthreads();
    #pragma unroll
    for (int i = 0; i < 32; i += 8) {
        float v = t[x][y + i];
        uint32_t hb = f2bf_bits(v);
        float lo = v - bf_bits2f(hb);
        size_t o = (size_t)(bn + y + i) * DMODEL + bk + x;
        Th[o] = __ushort_as_bfloat16((unsigned short)hb);
        Tl[o] = __float2bfloat16(lo);
    }
}

// ---------------------------------------------------------------------------
// Activation fp32 -> bf16 hi/lo split (elementwise)
// ---------------------------------------------------------------------------
__global__ __launch_bounds__(256) void asplit_k(const float* __restrict__ in,
                                                __nv_bfloat16* __restrict__ oh,
                                                __nv_bfloat16* __restrict__ ol)
{
    size_t i = ((size_t)blockIdx.x * 256 + threadIdx.x) * 4;
    float4 v = *(const float4*)(in + i);
    uint32_t h0 = f2bf_bits(v.x), h1 = f2bf_bits(v.y);
    uint32_t h2 = f2bf_bits(v.z), h3 = f2bf_bits(v.w);
    uint32_t l0 = f2bf_bits(v.x - bf_bits2f(h0));
    uint32_t l1 = f2bf_bits(v.y - bf_bits2f(h1));
    uint32_t l2 = f2bf_bits(v.z - bf_bits2f(h2));
    uint32_t l3 = f2bf_bits(v.w - bf_bits2f(h3));
    *(uint2*)(oh + i) = make_uint2(h0 | (h1 << 16), h2 | (h3 << 16));
    *(uint2*)(ol + i) = make_uint2(l0 | (l1 << 16), l2 | (l3 << 16));
}

// ---------------------------------------------------------------------------
// Tensor-core GEMM via mma.sync (bf16 3-product split, fp32 accumulate)
//   C[M=16384][N=1024] = alpha * (A @ Bt^T) (+res)
//   A hi/lo bf16 [M][K]; Bt hi/lo bf16 [N][K]. CTA tile 128x128, BK=32.
// ---------------------------------------------------------------------------
#define GBK    32
#define GPITCH 40                      // bf16 elements per smem row (80 B)
#define GTILE_B (128 * GPITCH * 2)     // 10240 B per tile
#define GSTAGE_B (4 * GTILE_B)         // Ah, Al, Bh, Bl = 40960 B

__global__ __launch_bounds__(256) void gemm_mma(
    const __nv_bfloat16* __restrict__ Ah, const __nv_bfloat16* __restrict__ Al,
    const __nv_bfloat16* __restrict__ Bh, const __nv_bfloat16* __restrict__ Bl,
    const float* __restrict__ res, float* __restrict__ C, float alpha)
{
    extern __shared__ char dsm[];
    const uint32_t sb = smem_u32(dsm);

    const int tid  = threadIdx.x;
    const int wid  = tid >> 5;
    const int lane = tid & 31;
    const int tM = blockIdx.y, tN = blockIdx.x;
    const int wm = wid & 1;        // 2 warp-rows (64 M each)
    const int wn = wid >> 1;       // 4 warp-cols (32 N each)

    // per-thread load coords: 2 chunks of 16B per tile per chunk-iter
    const int r0 = tid >> 2;              // 0..63
    const int c0 = (tid & 3);             // 16B chunk col 0..3
    // chunk i covers rows r (0..127), cols c (0..3)*8
    // thread handles i = tid and i = tid + 256 -> rows r0 and r0+64

    const __nv_bfloat16* Ahp = Ah + (size_t)(tM * 128) * DMODEL;
    const __nv_bfloat16* Alp = Al + (size_t)(tM * 128) * DMODEL;
    const __nv_bfloat16* Bhp = Bh + (size_t)(tN * 128) * DMODEL;
    const __nv_bfloat16* Blp = Bl + (size_t)(tN * 128) * DMODEL;

    float acc[4][4][4];
    #pragma unroll
    for (int i = 0; i < 4; i++)
        #pragma unroll
        for (int j = 0; j < 4; j++)
            #pragma unroll
            for (int t = 0; t < 4; t++) acc[i][j][t] = 0.0f;

    auto issue_chunk = [&](int c, int st) {
        const int k0 = c * GBK;
        uint32_t s = sb + st * GSTAGE_B;
        #pragma unroll
        for (int half = 0; half < 2; half++) {
            int r = r0 + half * 64;
            uint32_t so = (uint32_t)(r * (GPITCH * 2) + c0 * 16);
            size_t go = (size_t)r * DMODEL + k0 + c0 * 8;
            cpasync16(s + 0 * GTILE_B + so, Ahp + go);
            cpasync16(s + 1 * GTILE_B + so, Alp + go);
            cpasync16(s + 2 * GTILE_B + so, Bhp + go);
            cpasync16(s + 3 * GTILE_B + so, Blp + go);
        }
        CP_COMMIT();
    };

    issue_chunk(0, 0);

    const int NC = DMODEL / GBK;   // 32
    for (int c = 0; c < NC; c++) {
        const int st = c & 1;
        if (c + 1 < NC) { issue_chunk(c + 1, st ^ 1); CP_WAIT1(); }
        else            { CP_WAIT0(); }
        __syncthreads();

        uint32_t sAh = sb + st * GSTAGE_B;
        uint32_t sAl = sAh + GTILE_B;
        uint32_t sBh = sAh + 2 * GTILE_B;
        uint32_t sBl = sAh + 3 * GTILE_B;

        // ldmatrix lane address components
        const int a_row = (lane & 15);            // row within 16
        const int a_kh  = (lane >> 4) * 8;        // k half
        const int b_row = (lane & 7) + ((lane >> 4) << 3);  // row within 16
        const int b_kh  = ((lane >> 3) & 1) * 8;

        #pragma unroll
        for (int ks = 0; ks < 2; ks++) {
            const int kb = ks * 16;
            uint32_t ah[4][4], al[4][4], bh[4][2], bl[4][2];
            #pragma unroll
            for (int mt = 0; mt < 4; mt++) {
                uint32_t off = (uint32_t)((wm * 64 + mt * 16 + a_row) * (GPITCH * 2)
                                          + (kb + a_kh) * 2);
                LDSM4(ah[mt][0], ah[mt][1], ah[mt][2], ah[mt][3], sAh + off);
                LDSM4(al[mt][0], al[mt][1], al[mt][2], al[mt][3], sAl + off);
            }
            #pragma unroll
            for (int j = 0; j < 2; j++) {
                uint32_t off = (uint32_t)((wn * 32 + j * 16 + b_row) * (GPITCH * 2)
                                          + (kb + b_kh) * 2);
                LDSM4(bh[2*j][0], bh[2*j][1], bh[2*j+1][0], bh[2*j+1][1], sBh + off);
                LDSM4(bl[2*j][0], bl[2*j][1], bl[2*j+1][0], bl[2*j+1][1], sBl + off);
            }
            #pragma unroll
            for (int mt = 0; mt < 4; mt++)
                #pragma unroll
                for (int nt = 0; nt < 4; nt++) {
                    MMA16816(acc[mt][nt][0], acc[mt][nt][1], acc[mt][nt][2], acc[mt][nt][3],
                             ah[mt][0], ah[mt][1], ah[mt][2], ah[mt][3],
                             bh[nt][0], bh[nt][1]);
                    MMA16816(acc[mt][nt][0], acc[mt][nt][1], acc[mt][nt][2], acc[mt][nt][3],
                             ah[mt][0], ah[mt][1], ah[mt][2], ah[mt][3],
                             bl[nt][0], bl[nt][1]);
                    MMA16816(acc[mt][nt][0], acc[mt][nt][1], acc[mt][nt][2], acc[mt][nt][3],
                             al[mt][0], al[mt][1], al[mt][2], al[mt][3],
                             bh[nt][0], bh[nt][1]);
                }
        }
        __syncthreads();
    }

    // Epilogue
    #pragma unroll
    for (int mt = 0; mt < 4; mt++) {
        #pragma unroll
        for (int nt = 0; nt < 4; nt++) {
            int row = tM * 128 + wm * 64 + mt * 16 + (lane >> 2);
            int col = tN * 128 + wn * 32 + nt * 8 + (lane & 3) * 2;
            #pragma unroll
            for (int hh = 0; hh < 2; hh++) {
                size_t o = (size_t)(row + hh * 8) * DMODEL + col;
                float2 v;
                v.x = alpha * acc[mt][nt][hh * 2 + 0];
                v.y = alpha * acc[mt][nt][hh * 2 + 1];
                if (res) {
                    float2 rr = *(const float2*)(res + o);
                    v.x += rr.x; v.y += rr.y;
                }
                *(float2*)(C + o) = v;
            }
        }
    }
}

// ---------------------------------------------------------------------------
// Warp utils
// ---------------------------------------------------------------------------
__device__ __forceinline__ float warp_max(float v) {
    #pragma unroll
    for (int o = 16; o > 0; o >>= 1) v = fmaxf(v, __shfl_xor_sync(0xffffffffu, v, o));
    return v;
}
__device__ __forceinline__ float warp_sum(float v) {
    #pragma unroll
    for (int o = 16; o > 0; o >>= 1) v += __shfl_xor_sync(0xffffffffu, v, o);
    return v;
}

#define PCH 65  // smem pitch (64 + 1 pad)

// ---------------------------------------------------------------------------
// Local attention: one block per (b, seg, h).
// ---------------------------------------------------------------------------
__global__ __launch_bounds__(256) void attn_local_k()
{
    extern __shared__ float sm[];
    float* sq = sm;
    float* sk = sm + 64 * PCH;
    float* sv = sm + 2 * 64 * PCH;

    int bid = blockIdx.x;
    int h   = bid % NH;
    int seg = (bid / NH) % NSEG;
    int b   = bid / (NH * NSEG);
    int t0  = b * SLEN + seg * SEGLEN;
    int tid = threadIdx.x;

    for (int idx = tid; idx < 1024; idx += 256) {
        int r = idx >> 4;
        int c = (idx & 15) << 2;
        size_t g = (size_t)(t0 + r) * DMODEL + h * DH + c;
        float4 a = *(const float4*)(g_q + g);
        sq[r * PCH + c] = a.x; sq[r * PCH + c + 1] = a.y;
        sq[r * PCH + c + 2] = a.z; sq[r * PCH + c + 3] = a.w;
        float4 bb = *(const float4*)(g_k + g);
        sk[r * PCH + c] = bb.x; sk[r * PCH + c + 1] = bb.y;
        sk[r * PCH + c + 2] = bb.z; sk[r * PCH + c + 3] = bb.w;
        float4 vv = *(const float4*)(g_v + g);
        sv[r * PCH + c] = vv.x; sv[r * PCH + c + 1] = vv.y;
        sv[r * PCH + c + 2] = vv.z; sv[r * PCH + c + 3] = vv.w;
    }
    __syncthreads();

    int tx = tid & 15, ty = tid >> 4;
    float acc[4][4];
    #pragma unroll
    for (int i = 0; i < 4; i++)
        #pragma unroll
        for (int j = 0; j < 4; j++) acc[i][j] = 0.0f;

    for (int d = 0; d < 64; d++) {
        float qa[4], kb[4];
        #pragma unroll
        for (int i = 0; i < 4; i++) qa[i] = sq[(ty * 4 + i) * PCH + d];
        #pragma unroll
        for (int j = 0; j < 4; j++) kb[j] = sk[(tx * 4 + j) * PCH + d];
        #pragma unroll
        for (int i = 0; i < 4; i++)
            #pragma unroll
            for (int j = 0; j < 4; j++) acc[i][j] += qa[i] * kb[j];
    }
    __syncthreads();

    #pragma unroll
    for (int i = 0; i < 4; i++)
        #pragma unroll
        for (int j = 0; j < 4; j++)
            sq[(ty * 4 + i) * PCH + tx * 4 + j] = acc[i][j];
    __syncthreads();

    int warp = tid >> 5, lane = tid & 31;
    for (int r = warp; r < 64; r += 8) {
        float l0 = sq[r * PCH + lane];
        float l1 = sq[r * PCH + 32 + lane];
        float mx = warp_max(fmaxf(l0, l1));
        float k0 = (lane <= r)      ? l0 : -3e38f;
        float k1 = (lane + 32 <= r) ? l1 : -3e38f;
        float mm = warp_max(fmaxf(k0, k1));
        float e0 = __expf(l0 - mx), e1 = __expf(l1 - mx);
        float su = warp_sum(e0 + e1);
        float em0 = (lane <= r)      ? __expf(l0 - mm) : 0.0f;
        float em1 = (lane + 32 <= r) ? __expf(l1 - mm) : 0.0f;
        float ss = warp_sum(em0 + em1);
        float inv = 1.0f / su;
        sq[r * PCH + lane]      = e0 * inv;
        sq[r * PCH + 32 + lane] = e1 * inv;
        sk[r * PCH + lane]      = em0;
        sk[r * PCH + 32 + lane] = em1;
        if (lane == 0) {
            g_mloc[(t0 + r) * NH + h] = mm;
            g_sloc[(t0 + r) * NH + h] = ss;
        }
    }
    __syncthreads();

    float a1[4][4], a2[4][4];
    #pragma unroll
    for (int i = 0; i < 4; i++)
        #pragma unroll
        for (int j = 0; j < 4; j++) { a1[i][j] = 0.0f; a2[i][j] = 0.0f; }

    for (int j = 0; j < 64; j++) {
        float vv[4];
        #pragma unroll
        for (int jj = 0; jj < 4; jj++) vv[jj] = sv[j * PCH + tx * 4 + jj];
        #pragma unroll
        for (int ii = 0; ii < 4; ii++) {
            float pu = sq[(ty * 4 + ii) * PCH + j];
            float pm = sk[(ty * 4 + ii) * PCH + j];
            #pragma unroll
            for (int jj = 0; jj < 4; jj++) {
                a1[ii][jj] += pu * vv[jj];
                a2[ii][jj] += pm * vv[jj];
            }
        }
    }

    #pragma unroll
    for (int ii = 0; ii < 4; ii++) {
        size_t base = (size_t)(t0 + ty * 4 + ii) * DMODEL + h * DH + tx * 4;
        float4 o1 = {a1[ii][0], a1[ii][1], a1[ii][2], a1[ii][3]};
        float4 o2 = {a2[ii][0], a2[ii][1], a2[ii][2], a2[ii][3]};
        *(float4*)(g_ra + base) = o1;
        *(float4*)(g_la + base) = o2;
    }
}

// ---------------------------------------------------------------------------
// Global attention + merge: one block per (b, l, h).
// ---------------------------------------------------------------------------
__global__ __launch_bounds__(256) void attn_global_k()
{
    extern __shared__ float sm[];
    float* sq = sm;
    float* sk = sm + 64 * PCH;
    float* sr = sm + 2 * 64 * PCH;
    __shared__ float s_cl[64], s_cg[64];

    int bid = blockIdx.x;
    int h   = bid % NH;
    int l   = (bid / NH) % SEGLEN;
    int b   = bid / (NH * SEGLEN);
    int tid = threadIdx.x;

    for (int idx = tid; idx < 1024; idx += 256) {
        int r = idx >> 4;
        int c = (idx & 15) << 2;
        size_t g = (size_t)(b * SLEN + r * SEGLEN + l) * DMODEL + h * DH + c;
        float4 a = *(const float4*)(g_q + g);
        sq[r * PCH + c] = a.x; sq[r * PCH + c + 1] = a.y;
        sq[r * PCH + c + 2] = a.z; sq[r * PCH + c + 3] = a.w;
        float4 kk = *(const float4*)(g_k2 + g);
        sk[r * PCH + c] = kk.x; sk[r * PCH + c + 1] = kk.y;
        sk[r * PCH + c + 2] = kk.z; sk[r * PCH + c + 3] = kk.w;
        float4 rr = *(const float4*)(g_ra + g);
        sr[r * PCH + c] = rr.x; sr[r * PCH + c + 1] = rr.y;
        sr[r * PCH + c + 2] = rr.z; sr[r * PCH + c + 3] = rr.w;
    }
    __syncthreads();

    int tx = tid & 15, ty = tid >> 4;
    float acc[4][4];
    #pragma unroll
    for (int i = 0; i < 4; i++)
        #pragma unroll
        for (int j = 0; j < 4; j++) acc[i][j] = 0.0f;

    for (int d = 0; d < 64; d++) {
        float qa[4], kb[4];
        #pragma unroll
        for (int i = 0; i < 4; i++) qa[i] = sq[(ty * 4 + i) * PCH + d];
        #pragma unroll
        for (int j = 0; j < 4; j++) kb[j] = sk[(tx * 4 + j) * PCH + d];
        #pragma unroll
        for (int i = 0; i < 4; i++)
            #pragma unroll
            for (int j = 0; j < 4; j++) acc[i][j] += qa[i] * kb[j];
    }
    __syncthreads();

    #pragma unroll
    for (int ii = 0; ii < 4; ii++)
        #pragma unroll
        for (int jj = 0; jj < 4; jj++) {
            int i = ty * 4 + ii, j = tx * 4 + jj;
            sq[i * PCH + j] = acc[ii][jj] + ((j >= i) ? NEGINF : 0.0f);
        }
    __syncthreads();

    int warp = tid >> 5, lane = tid & 31;
    for (int r = warp; r < 64; r += 8) {
        float l0 = sq[r * PCH + lane];
        float l1 = sq[r * PCH + 32 + lane];
        float mg = warp_max(fmaxf(l0, l1));
        float e0 = __expf(l0 - mg), e1 = __expf(l1 - mg);
        float sg = warp_sum(e0 + e1);
        sq[r * PCH + lane]      = e0;
        sq[r * PCH + 32 + lane] = e1;
        if (lane == 0) {
            int t = b * SLEN + r * SEGLEN + l;
            float mlc = g_mloc[t * NH + h];
            float slc = g_sloc[t * NH + h];
            float m  = fmaxf(mlc, mg);
            float al = __expf(mlc - m);
            float ag = __expf(mg - m);
            float inv = 1.0f / (slc * al + sg * ag);
            s_cl[r] = al * inv;
            s_cg[r] = ag * inv;
        }
    }
    __syncthreads();

    float ga[4][4];
    #pragma unroll
    for (int i = 0; i < 4; i++)
        #pragma unroll
        for (int j = 0; j < 4; j++) ga[i][j] = 0.0f;

    for (int j = 0; j < 64; j++) {
        float rv[4];
        #pragma unroll
        for (int jj = 0; jj < 4; jj++) rv[jj] = sr[j * PCH + tx * 4 + jj];
        #pragma unroll
        for (int ii = 0; ii < 4; ii++) {
            float p = sq[(ty * 4 + ii) * PCH + j];
            #pragma unroll
            for (int jj = 0; jj < 4; jj++) ga[ii][jj] += p * rv[jj];
        }
    }

    #pragma unroll
    for (int ii = 0; ii < 4; ii++) {
        int i = ty * 4 + ii;
        size_t base = (size_t)(b * SLEN + i * SEGLEN + l) * DMODEL + h * DH + tx * 4;
        float4 la = *(const float4*)(g_la + base);
        float cl = s_cl[i], cg = s_cg[i];
        float4 o;
        o.x = cl * la.x + cg * ga[ii][0];
        o.y = cl * la.y + cg * ga[ii][1];
        o.z = cl * la.z + cg * ga[ii][2];
        o.w = cl * la.w + cg * ga[ii][3];
        *(float4*)(g_mg + base) = o;
    }
}

// ---------------------------------------------------------------------------
// LayerNorm (in place): one block per token row of 1024
// ---------------------------------------------------------------------------
__global__ __launch_bounds__(256) void ln_k(float* __restrict__ x,
                                            const float* __restrict__ sc,
                                            const float* __restrict__ bs)
{
    size_t row = blockIdx.x;
    float* p = x + row * DMODEL;
    int c = threadIdx.x * 4;
    float4 v = *(float4*)(p + c);
    float s  = v.x + v.y + v.z + v.w;
    float sq = v.x * v.x + v.y * v.y + v.z * v.z + v.w * v.w;
    s  = warp_sum(s);
    sq = warp_sum(sq);
    __shared__ float rs[8], rq[8];
    int warp = threadIdx.x >> 5, lane = threadIdx.x & 31;
    if (lane == 0) { rs[warp] = s; rq[warp] = sq; }
    __syncthreads();
    if (warp == 0) {
        float a = (lane < 8) ? rs[lane] : 0.0f;
        float b = (lane < 8) ? rq[lane] : 0.0f;
        a = warp_sum(a);
        b = warp_sum(b);
        if (lane == 0) { rs[0] = a; rq[0] = b; }
    }
    __syncthreads();
    float mean = rs[0] * (1.0f / DMODEL);
    float var  = rq[0] * (1.0f / DMODEL) - mean * mean;
    float inv  = rsqrtf(var + 1e-6f);
    float4 g = *(const float4*)(sc + c);
    float4 b4 = *(const float4*)(bs + c);
    v.x = (v.x - mean) * inv * g.x + b4.x;
    v.y = (v.y - mean) * inv * g.y + b4.y;
    v.z = (v.z - mean) * inv * g.z + b4.z;
    v.w = (v.w - mean) * inv * g.w + b4.w;
    *(float4*)(p + c) = v;
}

// ---------------------------------------------------------------------------
// Host launcher
// ---------------------------------------------------------------------------
extern "C" void kernel_launch(void* const* d_in, const int* in_sizes, int n_in,
                              void* d_out, int out_size)
{
    const float* x    = (const float*)d_in[0];
    const float* Wq   = (const float*)d_in[1];
    const float* Wk   = (const float*)d_in[2];
    const float* Wv   = (const float*)d_in[3];
    const float* Wrow = (const float*)d_in[4];
    const float* lns  = (const float*)d_in[5];
    const float* lnb  = (const float*)d_in[6];
    const float* Wk2  = (const float*)d_in[7];
    const float* Wout = (const float*)d_in[8];
    float* out = (float*)d_out;

    float *q, *k, *v, *ra, *la, *kt, *k2, *mg;
    cudaGetSymbolAddress((void**)&q,  g_q);
    cudaGetSymbolAddress((void**)&k,  g_k);
    cudaGetSymbolAddress((void**)&v,  g_v);
    cudaGetSymbolAddress((void**)&ra, g_ra);
    cudaGetSymbolAddress((void**)&la, g_la);
    cudaGetSymbolAddress((void**)&kt, g_kt);
    cudaGetSymbolAddress((void**)&k2, g_k2);
    cudaGetSymbolAddress((void**)&mg, g_mg);

    __nv_bfloat16 *wh, *wl, *ah, *al;
    cudaGetSymbolAddress((void**)&wh, g_wh);
    cudaGetSymbolAddress((void**)&wl, g_wl);
    cudaGetSymbolAddress((void**)&ah, g_ah);
    cudaGetSymbolAddress((void**)&al, g_al);
    const size_t WSZ = (size_t)DMODEL * DMODEL;

    const int ATT_SMEM = 3 * 64 * PCH * (int)sizeof(float);
    cudaFuncSetAttribute(attn_local_k,  cudaFuncAttributeMaxDynamicSharedMemorySize, ATT_SMEM);
    cudaFuncSetAttribute(attn_global_k, cudaFuncAttributeMaxDynamicSharedMemorySize, ATT_SMEM);

    const int GEMM_SMEM = 2 * GSTAGE_B;   // 81920
    cudaFuncSetAttribute(gemm_mma, cudaFuncAttributeMaxDynamicSharedMemorySize, GEMM_SMEM);

    // weight prep
    dim3 wsg(32, 32), wst(256);
    const float* Ws[6] = {Wq, Wk, Wv, Wrow, Wk2, Wout};
    for (int i = 0; i < 6; i++)
        wsplit_k<<<wsg, wst>>>(Ws[i], wh + i * WSZ, wl + i * WSZ);

    dim3 gg(DMODEL / 128, NTOK / 128);   // (8, 128)
    dim3 bt(256);
    const int ASPLIT_G = (NTOK * DMODEL) / (256 * 4);

    // x -> hi/lo, then q/k/v projections (q scaled by 0.125)
    asplit_k<<<ASPLIT_G, 256>>>(x, ah, al);
    gemm_mma<<<gg, bt, GEMM_SMEM>>>(ah, al, wh + 0 * WSZ, wl + 0 * WSZ, nullptr, q, 0.125f);
    gemm_mma<<<gg, bt, GEMM_SMEM>>>(ah, al, wh + 1 * WSZ, wl + 1 * WSZ, nullptr, k, 1.0f);
    gemm_mma<<<gg, bt, GEMM_SMEM>>>(ah, al, wh + 2 * WSZ, wl + 2 * WSZ, nullptr, v, 1.0f);

    attn_local_k<<<NBATCH * NSEG * NH, 256, ATT_SMEM>>>();

    asplit_k<<<ASPLIT_G, 256>>>(ra, ah, al);
    gemm_mma<<<gg, bt, GEMM_SMEM>>>(ah, al, wh + 3 * WSZ, wl + 3 * WSZ, x, kt, 1.0f);
    ln_k<<<NTOK, 256>>>(kt, lns, lnb);
    asplit_k<<<ASPLIT_G, 256>>>(kt, ah, al);
    gemm_mma<<<gg, bt, GEMM_SMEM>>>(ah, al, wh + 4 * WSZ, wl + 4 * WSZ, nullptr, k2, 1.0f);

    attn_global_k<<<NBATCH * SEGLEN * NH, 256, ATT_SMEM>>>();

    asplit_k<<<ASPLIT_G, 256>>>(mg, ah, al);
    gemm_mma<<<gg, bt, GEMM_SMEM>>>(ah, al, wh + 5 * WSZ, wl + 5 * WSZ, nullptr, out, 1.0f);
}

// round 5
// speedup vs baseline: 3.0038x; 1.3079x over previous
#include <cuda_runtime.h>
#include <cuda_fp16.h>
#include <cstdint>

// ---------------------------------------------------------------------------
// Problem constants
// ---------------------------------------------------------------------------
#define NTOK   16384      // B*S
#define DMODEL 1024
#define NH     16
#define DH     64
#define SEGLEN 64
#define NSEG   64
#define SLEN   4096
#define NBATCH 4
#define NEGINF -1e10f

// ---------------------------------------------------------------------------
// Scratch (device globals)
// ---------------------------------------------------------------------------
__device__ float g_q [NTOK * DMODEL];
__device__ float g_k [NTOK * DMODEL];
__device__ float g_v [NTOK * DMODEL];
__device__ float g_ra[NTOK * DMODEL];
__device__ float g_la[NTOK * DMODEL];
__device__ float g_kt[NTOK * DMODEL];
__device__ float g_k2[NTOK * DMODEL];
__device__ float g_mloc[NTOK * NH];
__device__ float g_sloc[NTOK * NH];

// Pre-transposed fp16 weights: [6][N=1024][K=1024]
__device__ __half g_w16[6][DMODEL * DMODEL];
// Activation fp16 hi/lo (reused across GEMMs; producers write these directly)
__device__ __half g_ah[NTOK * DMODEL];
__device__ __half g_al[NTOK * DMODEL];

// ---------------------------------------------------------------------------
// Helpers
// ---------------------------------------------------------------------------
__device__ __forceinline__ uint32_t smem_u32(const void* p) {
    uint32_t a;
    asm("{ .reg .u64 t; cvta.to.shared.u64 t, %1; cvt.u32.u64 %0, t; }"
        : "=r"(a) : "l"(p));
    return a;
}
__device__ __forceinline__ void cpasync16(uint32_t s, const void* g) {
    asm volatile("cp.async.cg.shared.global [%0], [%1], 16;" :: "r"(s), "l"(g));
}
#define CP_COMMIT() asm volatile("cp.async.commit_group;")
#define CP_WAIT1()  asm volatile("cp.async.wait_group 1;")
#define CP_WAIT0()  asm volatile("cp.async.wait_group 0;")

#define LDSM4(r0, r1, r2, r3, addr) \
    asm volatile("ldmatrix.sync.aligned.m8n8.x4.shared.b16 {%0,%1,%2,%3}, [%4];" \
                 : "=r"(r0), "=r"(r1), "=r"(r2), "=r"(r3) : "r"(addr))

#define MMA16816(c0, c1, c2, c3, a0, a1, a2, a3, b0, b1) \
    asm volatile("mma.sync.aligned.m16n8k16.row.col.f32.f16.f16.f32 " \
                 "{%0,%1,%2,%3}, {%4,%5,%6,%7}, {%8,%9}, {%0,%1,%2,%3};" \
                 : "+f"(c0), "+f"(c1), "+f"(c2), "+f"(c3) \
                 : "r"(a0), "r"(a1), "r"(a2), "r"(a3), "r"(b0), "r"(b1))

__device__ __forceinline__ uint32_t hbits(float v) {
    return (uint32_t)__half_as_ushort(__float2half(v));
}
// split v into fp16 hi/lo bit pairs
__device__ __forceinline__ void hsplit(float v, uint32_t& h, uint32_t& l) {
    __half hh = __float2half(v);
    h = (uint32_t)__half_as_ushort(hh);
    l = (uint32_t)__half_as_ushort(__float2half(v - __half2float(hh)));
}

// ---------------------------------------------------------------------------
// Weight transpose + fp16 convert:  W[K][N] -> T[N][K] fp16
// ---------------------------------------------------------------------------
__global__ __launch_bounds__(256) void wprep_k(const float* __restrict__ W,
                                               __half* __restrict__ T)
{
    __shared__ float t[32][33];
    int bn = blockIdx.x * 32;
    int bk = blockIdx.y * 32;
    int x = threadIdx.x & 31;
    int y = threadIdx.x >> 5;
    #pragma unroll
    for (int i = 0; i < 32; i += 8)
        t[y + i][x] = W[(size_t)(bk + y + i) * DMODEL + bn + x];
    __syncthreads();
    #pragma unroll
    for (int i = 0; i < 32; i += 8) {
        float v = t[x][y + i];
        T[(size_t)(bn + y + i) * DMODEL + bk + x] = __float2half(v);
    }
}

// ---------------------------------------------------------------------------
// Activation fp32 -> fp16 hi/lo split (only used for the input x)
// ---------------------------------------------------------------------------
__global__ __launch_bounds__(256) void asplit_k(const float* __restrict__ in,
                                                __half* __restrict__ oh,
                                                __half* __restrict__ ol)
{
    size_t i = ((size_t)blockIdx.x * 256 + threadIdx.x) * 4;
    float4 v = *(const float4*)(in + i);
    uint32_t h0, l0, h1, l1, h2, l2, h3, l3;
    hsplit(v.x, h0, l0); hsplit(v.y, h1, l1);
    hsplit(v.z, h2, l2); hsplit(v.w, h3, l3);
    *(uint2*)(oh + i) = make_uint2(h0 | (h1 << 16), h2 | (h3 << 16));
    *(uint2*)(ol + i) = make_uint2(l0 | (l1 << 16), l2 | (l3 << 16));
}

// ---------------------------------------------------------------------------
// Tensor-core GEMM (fp16 2-product: A = ah+al split, B single fp16)
//   C[M][N] = alpha * (A @ Bt^T) (+res)   CTA tile 128x128, BK=32.
// ---------------------------------------------------------------------------
#define GBK    32
#define GPITCH 40                      // fp16 elements per smem row (80 B)
#define GTILE_B (128 * GPITCH * 2)     // 10240 B per tile
#define GSTAGE_B (3 * GTILE_B)         // Ah, Al, B = 30720 B

__global__ __launch_bounds__(256) void gemm_mma(
    const __half* __restrict__ Ah, const __half* __restrict__ Al,
    const __half* __restrict__ Bf,
    const float* __restrict__ res, float* __restrict__ C, float alpha)
{
    extern __shared__ char dsm[];
    const uint32_t sb = smem_u32(dsm);

    const int tid  = threadIdx.x;
    const int wid  = tid >> 5;
    const int lane = tid & 31;
    const int tM = blockIdx.y, tN = blockIdx.x;
    const int wm = wid & 1;        // 2 warp-rows (64 M each)
    const int wn = wid >> 1;       // 4 warp-cols (32 N each)

    const int r0 = tid >> 2;              // 0..63
    const int c0 = (tid & 3);             // 16B chunk col 0..3

    const __half* Ahp = Ah + (size_t)(tM * 128) * DMODEL;
    const __half* Alp = Al + (size_t)(tM * 128) * DMODEL;
    const __half* Bp  = Bf + (size_t)(tN * 128) * DMODEL;

    float acc[4][4][4];
    #pragma unroll
    for (int i = 0; i < 4; i++)
        #pragma unroll
        for (int j = 0; j < 4; j++)
            #pragma unroll
            for (int t = 0; t < 4; t++) acc[i][j][t] = 0.0f;

    auto issue_chunk = [&](int c, int st) {
        const int k0 = c * GBK;
        uint32_t s = sb + st * GSTAGE_B;
        #pragma unroll
        for (int half = 0; half < 2; half++) {
            int r = r0 + half * 64;
            uint32_t so = (uint32_t)(r * (GPITCH * 2) + c0 * 16);
            size_t go = (size_t)r * DMODEL + k0 + c0 * 8;
            cpasync16(s + 0 * GTILE_B + so, Ahp + go);
            cpasync16(s + 1 * GTILE_B + so, Alp + go);
            cpasync16(s + 2 * GTILE_B + so, Bp  + go);
        }
        CP_COMMIT();
    };

    issue_chunk(0, 0);

    const int NC = DMODEL / GBK;   // 32
    for (int c = 0; c < NC; c++) {
        const int st = c & 1;
        if (c + 1 < NC) { issue_chunk(c + 1, st ^ 1); CP_WAIT1(); }
        else            { CP_WAIT0(); }
        __syncthreads();

        uint32_t sAh = sb + st * GSTAGE_B;
        uint32_t sAl = sAh + GTILE_B;
        uint32_t sB  = sAh + 2 * GTILE_B;

        const int a_row = (lane & 15);
        const int a_kh  = (lane >> 4) * 8;
        const int b_row = (lane & 7) + ((lane >> 4) << 3);
        const int b_kh  = ((lane >> 3) & 1) * 8;

        #pragma unroll
        for (int ks = 0; ks < 2; ks++) {
            const int kb = ks * 16;
            uint32_t ah[4][4], al[4][4], bb[4][2];
            #pragma unroll
            for (int mt = 0; mt < 4; mt++) {
                uint32_t off = (uint32_t)((wm * 64 + mt * 16 + a_row) * (GPITCH * 2)
                                          + (kb + a_kh) * 2);
                LDSM4(ah[mt][0], ah[mt][1], ah[mt][2], ah[mt][3], sAh + off);
                LDSM4(al[mt][0], al[mt][1], al[mt][2], al[mt][3], sAl + off);
            }
            #pragma unroll
            for (int j = 0; j < 2; j++) {
                uint32_t off = (uint32_t)((wn * 32 + j * 16 + b_row) * (GPITCH * 2)
                                          + (kb + b_kh) * 2);
                LDSM4(bb[2*j][0], bb[2*j][1], bb[2*j+1][0], bb[2*j+1][1], sB + off);
            }
            #pragma unroll
            for (int mt = 0; mt < 4; mt++)
                #pragma unroll
                for (int nt = 0; nt < 4; nt++) {
                    MMA16816(acc[mt][nt][0], acc[mt][nt][1], acc[mt][nt][2], acc[mt][nt][3],
                             ah[mt][0], ah[mt][1], ah[mt][2], ah[mt][3],
                             bb[nt][0], bb[nt][1]);
                    MMA16816(acc[mt][nt][0], acc[mt][nt][1], acc[mt][nt][2], acc[mt][nt][3],
                             al[mt][0], al[mt][1], al[mt][2], al[mt][3],
                             bb[nt][0], bb[nt][1]);
                }
        }
        __syncthreads();
    }

    // Epilogue
    #pragma unroll
    for (int mt = 0; mt < 4; mt++) {
        #pragma unroll
        for (int nt = 0; nt < 4; nt++) {
            int row = tM * 128 + wm * 64 + mt * 16 + (lane >> 2);
            int col = tN * 128 + wn * 32 + nt * 8 + (lane & 3) * 2;
            #pragma unroll
            for (int hh = 0; hh < 2; hh++) {
                size_t o = (size_t)(row + hh * 8) * DMODEL + col;
                float2 v;
                v.x = alpha * acc[mt][nt][hh * 2 + 0];
                v.y = alpha * acc[mt][nt][hh * 2 + 1];
                if (res) {
                    float2 rr = *(const float2*)(res + o);
                    v.x += rr.x; v.y += rr.y;
                }
                *(float2*)(C + o) = v;
            }
        }
    }
}

// ---------------------------------------------------------------------------
// Warp utils
// ---------------------------------------------------------------------------
__device__ __forceinline__ float warp_max(float v) {
    #pragma unroll
    for (int o = 16; o > 0; o >>= 1) v = fmaxf(v, __shfl_xor_sync(0xffffffffu, v, o));
    return v;
}
__device__ __forceinline__ float warp_sum(float v) {
    #pragma unroll
    for (int o = 16; o > 0; o >>= 1) v += __shfl_xor_sync(0xffffffffu, v, o);
    return v;
}

#define PCH 65  // smem pitch (64 + 1 pad)

// ---------------------------------------------------------------------------
// Local attention: one block per (b, seg, h).
// Writes: g_ra f32 + (g_ah,g_al fp16 split of ra), g_la f32, g_mloc, g_sloc
// ---------------------------------------------------------------------------
__global__ __launch_bounds__(256) void attn_local_k()
{
    extern __shared__ float sm[];
    float* sq = sm;
    float* sk = sm + 64 * PCH;
    float* sv = sm + 2 * 64 * PCH;

    int bid = blockIdx.x;
    int h   = bid % NH;
    int seg = (bid / NH) % NSEG;
    int b   = bid / (NH * NSEG);
    int t0  = b * SLEN + seg * SEGLEN;
    int tid = threadIdx.x;

    for (int idx = tid; idx < 1024; idx += 256) {
        int r = idx >> 4;
        int c = (idx & 15) << 2;
        size_t g = (size_t)(t0 + r) * DMODEL + h * DH + c;
        float4 a = *(const float4*)(g_q + g);
        sq[r * PCH + c] = a.x; sq[r * PCH + c + 1] = a.y;
        sq[r * PCH + c + 2] = a.z; sq[r * PCH + c + 3] = a.w;
        float4 bb = *(const float4*)(g_k + g);
        sk[r * PCH + c] = bb.x; sk[r * PCH + c + 1] = bb.y;
        sk[r * PCH + c + 2] = bb.z; sk[r * PCH + c + 3] = bb.w;
        float4 vv = *(const float4*)(g_v + g);
        sv[r * PCH + c] = vv.x; sv[r * PCH + c + 1] = vv.y;
        sv[r * PCH + c + 2] = vv.z; sv[r * PCH + c + 3] = vv.w;
    }
    __syncthreads();

    int tx = tid & 15, ty = tid >> 4;
    float acc[4][4];
    #pragma unroll
    for (int i = 0; i < 4; i++)
        #pragma unroll
        for (int j = 0; j < 4; j++) acc[i][j] = 0.0f;

    for (int d = 0; d < 64; d++) {
        float qa[4], kb[4];
        #pragma unroll
        for (int i = 0; i < 4; i++) qa[i] = sq[(ty * 4 + i) * PCH + d];
        #pragma unroll
        for (int j = 0; j < 4; j++) kb[j] = sk[(tx * 4 + j) * PCH + d];
        #pragma unroll
        for (int i = 0; i < 4; i++)
            #pragma unroll
            for (int j = 0; j < 4; j++) acc[i][j] += qa[i] * kb[j];
    }
    __syncthreads();

    #pragma unroll
    for (int i = 0; i < 4; i++)
        #pragma unroll
        for (int j = 0; j < 4; j++)
            sq[(ty * 4 + i) * PCH + tx * 4 + j] = acc[i][j];
    __syncthreads();

    int warp = tid >> 5, lane = tid & 31;
    for (int r = warp; r < 64; r += 8) {
        float l0 = sq[r * PCH + lane];
        float l1 = sq[r * PCH + 32 + lane];
        float mx = warp_max(fmaxf(l0, l1));
        float k0 = (lane <= r)      ? l0 : -3e38f;
        float k1 = (lane + 32 <= r) ? l1 : -3e38f;
        float mm = warp_max(fmaxf(k0, k1));
        float e0 = __expf(l0 - mx), e1 = __expf(l1 - mx);
        float su = warp_sum(e0 + e1);
        float em0 = (lane <= r)      ? __expf(l0 - mm) : 0.0f;
        float em1 = (lane + 32 <= r) ? __expf(l1 - mm) : 0.0f;
        float ss = warp_sum(em0 + em1);
        float inv = 1.0f / su;
        sq[r * PCH + lane]      = e0 * inv;
        sq[r * PCH + 32 + lane] = e1 * inv;
        sk[r * PCH + lane]      = em0;
        sk[r * PCH + 32 + lane] = em1;
        if (lane == 0) {
            g_mloc[(t0 + r) * NH + h] = mm;
            g_sloc[(t0 + r) * NH + h] = ss;
        }
    }
    __syncthreads();

    float a1[4][4], a2[4][4];
    #pragma unroll
    for (int i = 0; i < 4; i++)
        #pragma unroll
        for (int j = 0; j < 4; j++) { a1[i][j] = 0.0f; a2[i][j] = 0.0f; }

    for (int j = 0; j < 64; j++) {
        float vv[4];
        #pragma unroll
        for (int jj = 0; jj < 4; jj++) vv[jj] = sv[j * PCH + tx * 4 + jj];
        #pragma unroll
        for (int ii = 0; ii < 4; ii++) {
            float pu = sq[(ty * 4 + ii) * PCH + j];
            float pm = sk[(ty * 4 + ii) * PCH + j];
            #pragma unroll
            for (int jj = 0; jj < 4; jj++) {
                a1[ii][jj] += pu * vv[jj];
                a2[ii][jj] += pm * vv[jj];
            }
        }
    }

    #pragma unroll
    for (int ii = 0; ii < 4; ii++) {
        size_t base = (size_t)(t0 + ty * 4 + ii) * DMODEL + h * DH + tx * 4;
        float4 o1 = {a1[ii][0], a1[ii][1], a1[ii][2], a1[ii][3]};
        float4 o2 = {a2[ii][0], a2[ii][1], a2[ii][2], a2[ii][3]};
        *(float4*)(g_ra + base) = o1;
        *(float4*)(g_la + base) = o2;
        uint32_t h0, l0, h1, l1, h2, l2, h3, l3;
        hsplit(o1.x, h0, l0); hsplit(o1.y, h1, l1);
        hsplit(o1.z, h2, l2); hsplit(o1.w, h3, l3);
        *(uint2*)(g_ah + base) = make_uint2(h0 | (h1 << 16), h2 | (h3 << 16));
        *(uint2*)(g_al + base) = make_uint2(l0 | (l1 << 16), l2 | (l3 << 16));
    }
}

// ---------------------------------------------------------------------------
// Global attention + merge: one block per (b, l, h).
// Writes merged directly as fp16 hi/lo split (g_ah/g_al).
// ---------------------------------------------------------------------------
__global__ __launch_bounds__(256) void attn_global_k()
{
    extern __shared__ float sm[];
    float* sq = sm;
    float* sk = sm + 64 * PCH;
    float* sr = sm + 2 * 64 * PCH;
    __shared__ float s_cl[64], s_cg[64];

    int bid = blockIdx.x;
    int h   = bid % NH;
    int l   = (bid / NH) % SEGLEN;
    int b   = bid / (NH * SEGLEN);
    int tid = threadIdx.x;

    for (int idx = tid; idx < 1024; idx += 256) {
        int r = idx >> 4;
        int c = (idx & 15) << 2;
        size_t g = (size_t)(b * SLEN + r * SEGLEN + l) * DMODEL + h * DH + c;
        float4 a = *(const float4*)(g_q + g);
        sq[r * PCH + c] = a.x; sq[r * PCH + c + 1] = a.y;
        sq[r * PCH + c + 2] = a.z; sq[r * PCH + c + 3] = a.w;
        float4 kk = *(const float4*)(g_k2 + g);
        sk[r * PCH + c] = kk.x; sk[r * PCH + c + 1] = kk.y;
        sk[r * PCH + c + 2] = kk.z; sk[r * PCH + c + 3] = kk.w;
        float4 rr = *(const float4*)(g_ra + g);
        sr[r * PCH + c] = rr.x; sr[r * PCH + c + 1] = rr.y;
        sr[r * PCH + c + 2] = rr.z; sr[r * PCH + c + 3] = rr.w;
    }
    __syncthreads();

    int tx = tid & 15, ty = tid >> 4;
    float acc[4][4];
    #pragma unroll
    for (int i = 0; i < 4; i++)
        #pragma unroll
        for (int j = 0; j < 4; j++) acc[i][j] = 0.0f;

    for (int d = 0; d < 64; d++) {
        float qa[4], kb[4];
        #pragma unroll
        for (int i = 0; i < 4; i++) qa[i] = sq[(ty * 4 + i) * PCH + d];
        #pragma unroll
        for (int j = 0; j < 4; j++) kb[j] = sk[(tx * 4 + j) * PCH + d];
        #pragma unroll
        for (int i = 0; i < 4; i++)
            #pragma unroll
            for (int j = 0; j < 4; j++) acc[i][j] += qa[i] * kb[j];
    }
    __syncthreads();

    #pragma unroll
    for (int ii = 0; ii < 4; ii++)
        #pragma unroll
        for (int jj = 0; jj < 4; jj++) {
            int i = ty * 4 + ii, j = tx * 4 + jj;
            sq[i * PCH + j] = acc[ii][jj] + ((j >= i) ? NEGINF : 0.0f);
        }
    __syncthreads();

    int warp = tid >> 5, lane = tid & 31;
    for (int r = warp; r < 64; r += 8) {
        float l0 = sq[r * PCH + lane];
        float l1 = sq[r * PCH + 32 + lane];
        float mg = warp_max(fmaxf(l0, l1));
        float e0 = __expf(l0 - mg), e1 = __expf(l1 - mg);
        float sg = warp_sum(e0 + e1);
        sq[r * PCH + lane]      = e0;
        sq[r * PCH + 32 + lane] = e1;
        if (lane == 0) {
            int t = b * SLEN + r * SEGLEN + l;
            float mlc = g_mloc[t * NH + h];
            float slc = g_sloc[t * NH + h];
            float m  = fmaxf(mlc, mg);
            float al = __expf(mlc - m);
            float ag = __expf(mg - m);
            float inv = 1.0f / (slc * al + sg * ag);
            s_cl[r] = al * inv;
            s_cg[r] = ag * inv;
        }
    }
    __syncthreads();

    float ga[4][4];
    #pragma unroll
    for (int i = 0; i < 4; i++)
        #pragma unroll
        for (int j = 0; j < 4; j++) ga[i][j] = 0.0f;

    for (int j = 0; j < 64; j++) {
        float rv[4];
        #pragma unroll
        for (int jj = 0; jj < 4; jj++) rv[jj] = sr[j * PCH + tx * 4 + jj];
        #pragma unroll
        for (int ii = 0; ii < 4; ii++) {
            float p = sq[(ty * 4 + ii) * PCH + j];
            #pragma unroll
            for (int jj = 0; jj < 4; jj++) ga[ii][jj] += p * rv[jj];
        }
    }

    #pragma unroll
    for (int ii = 0; ii < 4; ii++) {
        int i = ty * 4 + ii;
        size_t base = (size_t)(b * SLEN + i * SEGLEN + l) * DMODEL + h * DH + tx * 4;
        float4 la = *(const float4*)(g_la + base);
        float cl = s_cl[i], cg = s_cg[i];
        float4 o;
        o.x = cl * la.x + cg * ga[ii][0];
        o.y = cl * la.y + cg * ga[ii][1];
        o.z = cl * la.z + cg * ga[ii][2];
        o.w = cl * la.w + cg * ga[ii][3];
        uint32_t h0, l0, h1, l1, h2, l2, h3, l3;
        hsplit(o.x, h0, l0); hsplit(o.y, h1, l1);
        hsplit(o.z, h2, l2); hsplit(o.w, h3, l3);
        *(uint2*)(g_ah + base) = make_uint2(h0 | (h1 << 16), h2 | (h3 << 16));
        *(uint2*)(g_al + base) = make_uint2(l0 | (l1 << 16), l2 | (l3 << 16));
    }
}

// ---------------------------------------------------------------------------
// LayerNorm: reads kt f32, writes normalized result as fp16 hi/lo split
// ---------------------------------------------------------------------------
__global__ __launch_bounds__(256) void ln_k(const float* __restrict__ x,
                                            const float* __restrict__ sc,
                                            const float* __restrict__ bs,
                                            __half* __restrict__ oh,
                                            __half* __restrict__ ol)
{
    size_t row = blockIdx.x;
    const float* p = x + row * DMODEL;
    int c = threadIdx.x * 4;
    float4 v = *(const float4*)(p + c);
    float s  = v.x + v.y + v.z + v.w;
    float sq = v.x * v.x + v.y * v.y + v.z * v.z + v.w * v.w;
    s  = warp_sum(s);
    sq = warp_sum(sq);
    __shared__ float rs[8], rq[8];
    int warp = threadIdx.x >> 5, lane = threadIdx.x & 31;
    if (lane == 0) { rs[warp] = s; rq[warp] = sq; }
    __syncthreads();
    if (warp == 0) {
        float a = (lane < 8) ? rs[lane] : 0.0f;
        float b = (lane < 8) ? rq[lane] : 0.0f;
        a = warp_sum(a);
        b = warp_sum(b);
        if (lane == 0) { rs[0] = a; rq[0] = b; }
    }
    __syncthreads();
    float mean = rs[0] * (1.0f / DMODEL);
    float var  = rq[0] * (1.0f / DMODEL) - mean * mean;
    float inv  = rsqrtf(var + 1e-6f);
    float4 g = *(const float4*)(sc + c);
    float4 b4 = *(const float4*)(bs + c);
    v.x = (v.x - mean) * inv * g.x + b4.x;
    v.y = (v.y - mean) * inv * g.y + b4.y;
    v.z = (v.z - mean) * inv * g.z + b4.z;
    v.w = (v.w - mean) * inv * g.w + b4.w;
    uint32_t h0, l0, h1, l1, h2, l2, h3, l3;
    hsplit(v.x, h0, l0); hsplit(v.y, h1, l1);
    hsplit(v.z, h2, l2); hsplit(v.w, h3, l3);
    size_t o = row * DMODEL + c;
    *(uint2*)(oh + o) = make_uint2(h0 | (h1 << 16), h2 | (h3 << 16));
    *(uint2*)(ol + o) = make_uint2(l0 | (l1 << 16), l2 | (l3 << 16));
}

// ---------------------------------------------------------------------------
// Host launcher
// ---------------------------------------------------------------------------
extern "C" void kernel_launch(void* const* d_in, const int* in_sizes, int n_in,
                              void* d_out, int out_size)
{
    const float* x    = (const float*)d_in[0];
    const float* Wq   = (const float*)d_in[1];
    const float* Wk   = (const float*)d_in[2];
    const float* Wv   = (const float*)d_in[3];
    const float* Wrow = (const float*)d_in[4];
    const float* lns  = (const float*)d_in[5];
    const float* lnb  = (const float*)d_in[6];
    const float* Wk2  = (const float*)d_in[7];
    const float* Wout = (const float*)d_in[8];
    float* out = (float*)d_out;

    float *q, *k, *v, *ra, *kt, *k2;
    cudaGetSymbolAddress((void**)&q,  g_q);
    cudaGetSymbolAddress((void**)&k,  g_k);
    cudaGetSymbolAddress((void**)&v,  g_v);
    cudaGetSymbolAddress((void**)&ra, g_ra);
    cudaGetSymbolAddress((void**)&kt, g_kt);
    cudaGetSymbolAddress((void**)&k2, g_k2);

    __half *w16, *ah, *al;
    cudaGetSymbolAddress((void**)&w16, g_w16);
    cudaGetSymbolAddress((void**)&ah, g_ah);
    cudaGetSymbolAddress((void**)&al, g_al);
    const size_t WSZ = (size_t)DMODEL * DMODEL;

    const int ATT_SMEM = 3 * 64 * PCH * (int)sizeof(float);
    cudaFuncSetAttribute(attn_local_k,  cudaFuncAttributeMaxDynamicSharedMemorySize, ATT_SMEM);
    cudaFuncSetAttribute(attn_global_k, cudaFuncAttributeMaxDynamicSharedMemorySize, ATT_SMEM);

    const int GEMM_SMEM = 2 * GSTAGE_B;   // 61440
    cudaFuncSetAttribute(gemm_mma, cudaFuncAttributeMaxDynamicSharedMemorySize, GEMM_SMEM);

    // weight prep (transpose + fp16)
    dim3 wsg(32, 32), wst(256);
    const float* Ws[6] = {Wq, Wk, Wv, Wrow, Wk2, Wout};
    for (int i = 0; i < 6; i++)
        wprep_k<<<wsg, wst>>>(Ws[i], w16 + i * WSZ);

    dim3 gg(DMODEL / 128, NTOK / 128);   // (8, 128)
    dim3 bt(256);
    const int ASPLIT_G = (NTOK * DMODEL) / (256 * 4);

    // x -> hi/lo, then q/k/v projections (q scaled by 0.125)
    asplit_k<<<ASPLIT_G, 256>>>(x, ah, al);
    gemm_mma<<<gg, bt, GEMM_SMEM>>>(ah, al, w16 + 0 * WSZ, nullptr, q, 0.125f);
    gemm_mma<<<gg, bt, GEMM_SMEM>>>(ah, al, w16 + 1 * WSZ, nullptr, k, 1.0f);
    gemm_mma<<<gg, bt, GEMM_SMEM>>>(ah, al, w16 + 2 * WSZ, nullptr, v, 1.0f);

    // local attention: writes ra f32 + ra split into ah/al
    attn_local_k<<<NBATCH * NSEG * NH, 256, ATT_SMEM>>>();

    gemm_mma<<<gg, bt, GEMM_SMEM>>>(ah, al, w16 + 3 * WSZ, x, kt, 1.0f);
    ln_k<<<NTOK, 256>>>(kt, lns, lnb, ah, al);
    gemm_mma<<<gg, bt, GEMM_SMEM>>>(ah, al, w16 + 4 * WSZ, nullptr, k2, 1.0f);

    // global attention + merge: writes merged split into ah/al
    attn_global_k<<<NBATCH * SEGLEN * NH, 256, ATT_SMEM>>>();

    gemm_mma<<<gg, bt, GEMM_SMEM>>>(ah, al, w16 + 5 * WSZ, nullptr, out, 1.0f);
}

// round 6
// speedup vs baseline: 3.0645x; 1.0202x over previous
#include <cuda_runtime.h>
#include <cuda_fp16.h>
#include <cstdint>

// ---------------------------------------------------------------------------
// Problem constants
// ---------------------------------------------------------------------------
#define NTOK   16384      // B*S
#define DMODEL 1024
#define NH     16
#define DH     64
#define SEGLEN 64
#define NSEG   64
#define SLEN   4096
#define NBATCH 4
#define NEGINF -1e10f

// ---------------------------------------------------------------------------
// Scratch (device globals)
// ---------------------------------------------------------------------------
__device__ float g_qkv[3 * NTOK * DMODEL];   // q | k | v contiguous
__device__ float g_ra[NTOK * DMODEL];
__device__ float g_la[NTOK * DMODEL];
__device__ float g_kt[NTOK * DMODEL];
__device__ float g_k2[NTOK * DMODEL];
__device__ float g_mloc[NTOK * NH];
__device__ float g_sloc[NTOK * NH];

// Pre-transposed fp16 weights: [6][N=1024][K=1024] (Wq pre-scaled by 0.125)
__device__ __half g_w16[6][DMODEL * DMODEL];
// Activation fp16 hi/lo (reused across GEMMs; producers write these directly)
__device__ __half g_ah[NTOK * DMODEL];
__device__ __half g_al[NTOK * DMODEL];

// ---------------------------------------------------------------------------
// Helpers
// ---------------------------------------------------------------------------
__device__ __forceinline__ uint32_t smem_u32(const void* p) {
    uint32_t a;
    asm("{ .reg .u64 t; cvta.to.shared.u64 t, %1; cvt.u32.u64 %0, t; }"
        : "=r"(a) : "l"(p));
    return a;
}
__device__ __forceinline__ void cpasync16(uint32_t s, const void* g) {
    asm volatile("cp.async.cg.shared.global [%0], [%1], 16;" :: "r"(s), "l"(g));
}
#define CP_COMMIT() asm volatile("cp.async.commit_group;")
#define CP_WAIT1()  asm volatile("cp.async.wait_group 1;")
#define CP_WAIT0()  asm volatile("cp.async.wait_group 0;")

#define LDSM4(r0, r1, r2, r3, addr) \
    asm volatile("ldmatrix.sync.aligned.m8n8.x4.shared.b16 {%0,%1,%2,%3}, [%4];" \
                 : "=r"(r0), "=r"(r1), "=r"(r2), "=r"(r3) : "r"(addr))

#define MMA16816(c0, c1, c2, c3, a0, a1, a2, a3, b0, b1) \
    asm volatile("mma.sync.aligned.m16n8k16.row.col.f32.f16.f16.f32 " \
                 "{%0,%1,%2,%3}, {%4,%5,%6,%7}, {%8,%9}, {%0,%1,%2,%3};" \
                 : "+f"(c0), "+f"(c1), "+f"(c2), "+f"(c3) \
                 : "r"(a0), "r"(a1), "r"(a2), "r"(a3), "r"(b0), "r"(b1))

// split v into fp16 hi/lo bit pairs
__device__ __forceinline__ void hsplit(float v, uint32_t& h, uint32_t& l) {
    __half hh = __float2half(v);
    h = (uint32_t)__half_as_ushort(hh);
    l = (uint32_t)__half_as_ushort(__float2half(v - __half2float(hh)));
}

// ---------------------------------------------------------------------------
// Weight transpose + fp16 convert (with scale):  W[K][N] -> T[N][K] fp16
// ---------------------------------------------------------------------------
__global__ __launch_bounds__(256) void wprep_k(const float* __restrict__ W,
                                               __half* __restrict__ T,
                                               float scale)
{
    __shared__ float t[32][33];
    int bn = blockIdx.x * 32;
    int bk = blockIdx.y * 32;
    int x = threadIdx.x & 31;
    int y = threadIdx.x >> 5;
    #pragma unroll
    for (int i = 0; i < 32; i += 8)
        t[y + i][x] = W[(size_t)(bk + y + i) * DMODEL + bn + x];
    __syncthreads();
    #pragma unroll
    for (int i = 0; i < 32; i += 8) {
        float v = t[x][y + i] * scale;
        T[(size_t)(bn + y + i) * DMODEL + bk + x] = __float2half(v);
    }
}

// ---------------------------------------------------------------------------
// Activation fp32 -> fp16 hi/lo split (only used for the input x)
// ---------------------------------------------------------------------------
__global__ __launch_bounds__(256) void asplit_k(const float* __restrict__ in,
                                                __half* __restrict__ oh,
                                                __half* __restrict__ ol)
{
    size_t i = ((size_t)blockIdx.x * 256 + threadIdx.x) * 4;
    float4 v = *(const float4*)(in + i);
    uint32_t h0, l0, h1, l1, h2, l2, h3, l3;
    hsplit(v.x, h0, l0); hsplit(v.y, h1, l1);
    hsplit(v.z, h2, l2); hsplit(v.w, h3, l3);
    *(uint2*)(oh + i) = make_uint2(h0 | (h1 << 16), h2 | (h3 << 16));
    *(uint2*)(ol + i) = make_uint2(l0 | (l1 << 16), l2 | (l3 << 16));
}

// ---------------------------------------------------------------------------
// Tensor-core GEMM (fp16 2-product: A = ah+al split, B single fp16)
//   Out[tN>>3] tile: C + (tN>>3)*matStride, cols (tN&7)*128 ..
//   CTA tile 128x128, BK=32, 3-stage cp.async pipeline (1 barrier/chunk).
// ---------------------------------------------------------------------------
#define GBK    32
#define GPITCH 40                      // fp16 elements per smem row (80 B)
#define GTILE_B (128 * GPITCH * 2)     // 10240 B per tile
#define GSTAGE_B (3 * GTILE_B)         // Ah, Al, B = 30720 B
#define GSMEM   (3 * GSTAGE_B)         // 3 stages = 92160 B

__global__ __launch_bounds__(256) void gemm_mma(
    const __half* __restrict__ Ah, const __half* __restrict__ Al,
    const __half* __restrict__ Bf,
    const float* __restrict__ res, float* __restrict__ C, size_t matStride)
{
    extern __shared__ char dsm[];
    const uint32_t sb = smem_u32(dsm);

    const int tid  = threadIdx.x;
    const int wid  = tid >> 5;
    const int lane = tid & 31;
    const int tM = blockIdx.y, tN = blockIdx.x;
    const int wm = wid & 1;        // 2 warp-rows (64 M each)
    const int wn = wid >> 1;       // 4 warp-cols (32 N each)

    const int r0 = tid >> 2;              // 0..63
    const int c0 = (tid & 3);             // 16B chunk col 0..3

    const __half* Ahp = Ah + (size_t)(tM * 128) * DMODEL;
    const __half* Alp = Al + (size_t)(tM * 128) * DMODEL;
    const __half* Bp  = Bf + (size_t)(tN * 128) * DMODEL;

    float acc[4][4][4];
    #pragma unroll
    for (int i = 0; i < 4; i++)
        #pragma unroll
        for (int j = 0; j < 4; j++)
            #pragma unroll
            for (int t = 0; t < 4; t++) acc[i][j][t] = 0.0f;

    auto issue_chunk = [&](int c, int st) {
        const int k0 = c * GBK;
        uint32_t s = sb + st * GSTAGE_B;
        #pragma unroll
        for (int half = 0; half < 2; half++) {
            int r = r0 + half * 64;
            uint32_t so = (uint32_t)(r * (GPITCH * 2) + c0 * 16);
            size_t go = (size_t)r * DMODEL + k0 + c0 * 8;
            cpasync16(s + 0 * GTILE_B + so, Ahp + go);
            cpasync16(s + 1 * GTILE_B + so, Alp + go);
            cpasync16(s + 2 * GTILE_B + so, Bp  + go);
        }
        CP_COMMIT();
    };

    issue_chunk(0, 0);
    issue_chunk(1, 1);

    const int NC = DMODEL / GBK;   // 32
    for (int c = 0; c < NC; c++) {
        const int st = c % 3;
        if (c + 1 < NC) CP_WAIT1(); else CP_WAIT0();
        __syncthreads();
        if (c + 2 < NC) issue_chunk(c + 2, (c + 2) % 3);

        uint32_t sAh = sb + st * GSTAGE_B;
        uint32_t sAl = sAh + GTILE_B;
        uint32_t sB  = sAh + 2 * GTILE_B;

        const int a_row = (lane & 15);
        const int a_kh  = (lane >> 4) * 8;
        const int b_row = (lane & 7) + ((lane >> 4) << 3);
        const int b_kh  = ((lane >> 3) & 1) * 8;

        #pragma unroll
        for (int ks = 0; ks < 2; ks++) {
            const int kb = ks * 16;
            uint32_t ah[4][4], al[4][4], bb[4][2];
            #pragma unroll
            for (int mt = 0; mt < 4; mt++) {
                uint32_t off = (uint32_t)((wm * 64 + mt * 16 + a_row) * (GPITCH * 2)
                                          + (kb + a_kh) * 2);
                LDSM4(ah[mt][0], ah[mt][1], ah[mt][2], ah[mt][3], sAh + off);
                LDSM4(al[mt][0], al[mt][1], al[mt][2], al[mt][3], sAl + off);
            }
            #pragma unroll
            for (int j = 0; j < 2; j++) {
                uint32_t off = (uint32_t)((wn * 32 + j * 16 + b_row) * (GPITCH * 2)
                                          + (kb + b_kh) * 2);
                LDSM4(bb[2*j][0], bb[2*j][1], bb[2*j+1][0], bb[2*j+1][1], sB + off);
            }
            #pragma unroll
            for (int mt = 0; mt < 4; mt++)
                #pragma unroll
                for (int nt = 0; nt < 4; nt++) {
                    MMA16816(acc[mt][nt][0], acc[mt][nt][1], acc[mt][nt][2], acc[mt][nt][3],
                             ah[mt][0], ah[mt][1], ah[mt][2], ah[mt][3],
                             bb[nt][0], bb[nt][1]);
                    MMA16816(acc[mt][nt][0], acc[mt][nt][1], acc[mt][nt][2], acc[mt][nt][3],
                             al[mt][0], al[mt][1], al[mt][2], al[mt][3],
                             bb[nt][0], bb[nt][1]);
                }
        }
    }

    // Epilogue
    float* Cb = C + (size_t)(tN >> 3) * matStride;
    const int colb = (tN & 7) * 128;
    #pragma unroll
    for (int mt = 0; mt < 4; mt++) {
        #pragma unroll
        for (int nt = 0; nt < 4; nt++) {
            int row = tM * 128 + wm * 64 + mt * 16 + (lane >> 2);
            int col = colb + wn * 32 + nt * 8 + (lane & 3) * 2;
            #pragma unroll
            for (int hh = 0; hh < 2; hh++) {
                size_t o = (size_t)(row + hh * 8) * DMODEL + col;
                float2 v;
                v.x = acc[mt][nt][hh * 2 + 0];
                v.y = acc[mt][nt][hh * 2 + 1];
                if (res) {
                    float2 rr = *(const float2*)(res + o);
                    v.x += rr.x; v.y += rr.y;
                }
                *(float2*)(Cb + o) = v;
            }
        }
    }
}

// ---------------------------------------------------------------------------
// Warp utils
// ---------------------------------------------------------------------------
__device__ __forceinline__ float warp_max(float v) {
    #pragma unroll
    for (int o = 16; o > 0; o >>= 1) v = fmaxf(v, __shfl_xor_sync(0xffffffffu, v, o));
    return v;
}
__device__ __forceinline__ float warp_sum(float v) {
    #pragma unroll
    for (int o = 16; o > 0; o >>= 1) v += __shfl_xor_sync(0xffffffffu, v, o);
    return v;
}

#define PCH 65  // smem pitch (64 + 1 pad)

// ---------------------------------------------------------------------------
// Local attention: one block per (b, seg, h).
// Writes: g_ra f32 + (g_ah,g_al fp16 split of ra), g_la f32, g_mloc, g_sloc
// ---------------------------------------------------------------------------
__global__ __launch_bounds__(256, 4) void attn_local_k()
{
    extern __shared__ float sm[];
    float* sq = sm;
    float* sk = sm + 64 * PCH;
    float* sv = sm + 2 * 64 * PCH;

    const float* g_q = g_qkv;
    const float* g_k = g_qkv + (size_t)NTOK * DMODEL;
    const float* g_v = g_qkv + 2 * (size_t)NTOK * DMODEL;

    int bid = blockIdx.x;
    int h   = bid % NH;
    int seg = (bid / NH) % NSEG;
    int b   = bid / (NH * NSEG);
    int t0  = b * SLEN + seg * SEGLEN;
    int tid = threadIdx.x;

    for (int idx = tid; idx < 1024; idx += 256) {
        int r = idx >> 4;
        int c = (idx & 15) << 2;
        size_t g = (size_t)(t0 + r) * DMODEL + h * DH + c;
        float4 a = *(const float4*)(g_q + g);
        sq[r * PCH + c] = a.x; sq[r * PCH + c + 1] = a.y;
        sq[r * PCH + c + 2] = a.z; sq[r * PCH + c + 3] = a.w;
        float4 bb = *(const float4*)(g_k + g);
        sk[r * PCH + c] = bb.x; sk[r * PCH + c + 1] = bb.y;
        sk[r * PCH + c + 2] = bb.z; sk[r * PCH + c + 3] = bb.w;
        float4 vv = *(const float4*)(g_v + g);
        sv[r * PCH + c] = vv.x; sv[r * PCH + c + 1] = vv.y;
        sv[r * PCH + c + 2] = vv.z; sv[r * PCH + c + 3] = vv.w;
    }
    __syncthreads();

    int tx = tid & 15, ty = tid >> 4;
    float acc[4][4];
    #pragma unroll
    for (int i = 0; i < 4; i++)
        #pragma unroll
        for (int j = 0; j < 4; j++) acc[i][j] = 0.0f;

    for (int d = 0; d < 64; d++) {
        float qa[4], kb[4];
        #pragma unroll
        for (int i = 0; i < 4; i++) qa[i] = sq[(ty * 4 + i) * PCH + d];
        #pragma unroll
        for (int j = 0; j < 4; j++) kb[j] = sk[(tx * 4 + j) * PCH + d];
        #pragma unroll
        for (int i = 0; i < 4; i++)
            #pragma unroll
            for (int j = 0; j < 4; j++) acc[i][j] += qa[i] * kb[j];
    }
    __syncthreads();

    #pragma unroll
    for (int i = 0; i < 4; i++)
        #pragma unroll
        for (int j = 0; j < 4; j++)
            sq[(ty * 4 + i) * PCH + tx * 4 + j] = acc[i][j];
    __syncthreads();

    int warp = tid >> 5, lane = tid & 31;
    for (int r = warp; r < 64; r += 8) {
        float l0 = sq[r * PCH + lane];
        float l1 = sq[r * PCH + 32 + lane];
        float mx = warp_max(fmaxf(l0, l1));
        float k0 = (lane <= r)      ? l0 : -3e38f;
        float k1 = (lane + 32 <= r) ? l1 : -3e38f;
        float mm = warp_max(fmaxf(k0, k1));
        float e0 = __expf(l0 - mx), e1 = __expf(l1 - mx);
        float su = warp_sum(e0 + e1);
        float em0 = (lane <= r)      ? __expf(l0 - mm) : 0.0f;
        float em1 = (lane + 32 <= r) ? __expf(l1 - mm) : 0.0f;
        float ss = warp_sum(em0 + em1);
        float inv = 1.0f / su;
        sq[r * PCH + lane]      = e0 * inv;
        sq[r * PCH + 32 + lane] = e1 * inv;
        sk[r * PCH + lane]      = em0;
        sk[r * PCH + 32 + lane] = em1;
        if (lane == 0) {
            g_mloc[(t0 + r) * NH + h] = mm;
            g_sloc[(t0 + r) * NH + h] = ss;
        }
    }
    __syncthreads();

    float a1[4][4], a2[4][4];
    #pragma unroll
    for (int i = 0; i < 4; i++)
        #pragma unroll
        for (int j = 0; j < 4; j++) { a1[i][j] = 0.0f; a2[i][j] = 0.0f; }

    for (int j = 0; j < 64; j++) {
        float vv[4];
        #pragma unroll
        for (int jj = 0; jj < 4; jj++) vv[jj] = sv[j * PCH + tx * 4 + jj];
        #pragma unroll
        for (int ii = 0; ii < 4; ii++) {
            float pu = sq[(ty * 4 + ii) * PCH + j];
            float pm = sk[(ty * 4 + ii) * PCH + j];
            #pragma unroll
            for (int jj = 0; jj < 4; jj++) {
                a1[ii][jj] += pu * vv[jj];
                a2[ii][jj] += pm * vv[jj];
            }
        }
    }

    #pragma unroll
    for (int ii = 0; ii < 4; ii++) {
        size_t base = (size_t)(t0 + ty * 4 + ii) * DMODEL + h * DH + tx * 4;
        float4 o1 = {a1[ii][0], a1[ii][1], a1[ii][2], a1[ii][3]};
        float4 o2 = {a2[ii][0], a2[ii][1], a2[ii][2], a2[ii][3]};
        *(float4*)(g_ra + base) = o1;
        *(float4*)(g_la + base) = o2;
        uint32_t h0, l0, h1, l1, h2, l2, h3, l3;
        hsplit(o1.x, h0, l0); hsplit(o1.y, h1, l1);
        hsplit(o1.z, h2, l2); hsplit(o1.w, h3, l3);
        *(uint2*)(g_ah + base) = make_uint2(h0 | (h1 << 16), h2 | (h3 << 16));
        *(uint2*)(g_al + base) = make_uint2(l0 | (l1 << 16), l2 | (l3 << 16));
    }
}

// ---------------------------------------------------------------------------
// Global attention + merge: one block per (b, l, h).
// Writes merged directly as fp16 hi/lo split (g_ah/g_al).
// ---------------------------------------------------------------------------
__global__ __launch_bounds__(256, 4) void attn_global_k()
{
    extern __shared__ float sm[];
    float* sq = sm;
    float* sk = sm + 64 * PCH;
    float* sr = sm + 2 * 64 * PCH;
    __shared__ float s_cl[64], s_cg[64];

    const float* g_q = g_qkv;

    int bid = blockIdx.x;
    int h   = bid % NH;
    int l   = (bid / NH) % SEGLEN;
    int b   = bid / (NH * SEGLEN);
    int tid = threadIdx.x;

    for (int idx = tid; idx < 1024; idx += 256) {
        int r = idx >> 4;
        int c = (idx & 15) << 2;
        size_t g = (size_t)(b * SLEN + r * SEGLEN + l) * DMODEL + h * DH + c;
        float4 a = *(const float4*)(g_q + g);
        sq[r * PCH + c] = a.x; sq[r * PCH + c + 1] = a.y;
        sq[r * PCH + c + 2] = a.z; sq[r * PCH + c + 3] = a.w;
        float4 kk = *(const float4*)(g_k2 + g);
        sk[r * PCH + c] = kk.x; sk[r * PCH + c + 1] = kk.y;
        sk[r * PCH + c + 2] = kk.z; sk[r * PCH + c + 3] = kk.w;
        float4 rr = *(const float4*)(g_ra + g);
        sr[r * PCH + c] = rr.x; sr[r * PCH + c + 1] = rr.y;
        sr[r * PCH + c + 2] = rr.z; sr[r * PCH + c + 3] = rr.w;
    }
    __syncthreads();

    int tx = tid & 15, ty = tid >> 4;
    float acc[4][4];
    #pragma unroll
    for (int i = 0; i < 4; i++)
        #pragma unroll
        for (int j = 0; j < 4; j++) acc[i][j] = 0.0f;

    for (int d = 0; d < 64; d++) {
        float qa[4], kb[4];
        #pragma unroll
        for (int i = 0; i < 4; i++) qa[i] = sq[(ty * 4 + i) * PCH + d];
        #pragma unroll
        for (int j = 0; j < 4; j++) kb[j] = sk[(tx * 4 + j) * PCH + d];
        #pragma unroll
        for (int i = 0; i < 4; i++)
            #pragma unroll
            for (int j = 0; j < 4; j++) acc[i][j] += qa[i] * kb[j];
    }
    __syncthreads();

    #pragma unroll
    for (int ii = 0; ii < 4; ii++)
        #pragma unroll
        for (int jj = 0; jj < 4; jj++) {
            int i = ty * 4 + ii, j = tx * 4 + jj;
            sq[i * PCH + j] = acc[ii][jj] + ((j >= i) ? NEGINF : 0.0f);
        }
    __syncthreads();

    int warp = tid >> 5, lane = tid & 31;
    for (int r = warp; r < 64; r += 8) {
        float l0 = sq[r * PCH + lane];
        float l1 = sq[r * PCH + 32 + lane];
        float mg = warp_max(fmaxf(l0, l1));
        float e0 = __expf(l0 - mg), e1 = __expf(l1 - mg);
        float sg = warp_sum(e0 + e1);
        sq[r * PCH + lane]      = e0;
        sq[r * PCH + 32 + lane] = e1;
        if (lane == 0) {
            int t = b * SLEN + r * SEGLEN + l;
            float mlc = g_mloc[t * NH + h];
            float slc = g_sloc[t * NH + h];
            float m  = fmaxf(mlc, mg);
            float al = __expf(mlc - m);
            float ag = __expf(mg - m);
            float inv = 1.0f / (slc * al + sg * ag);
            s_cl[r] = al * inv;
            s_cg[r] = ag * inv;
        }
    }
    __syncthreads();

    float ga[4][4];
    #pragma unroll
    for (int i = 0; i < 4; i++)
        #pragma unroll
        for (int j = 0; j < 4; j++) ga[i][j] = 0.0f;

    for (int j = 0; j < 64; j++) {
        float rv[4];
        #pragma unroll
        for (int jj = 0; jj < 4; jj++) rv[jj] = sr[j * PCH + tx * 4 + jj];
        #pragma unroll
        for (int ii = 0; ii < 4; ii++) {
            float p = sq[(ty * 4 + ii) * PCH + j];
            #pragma unroll
            for (int jj = 0; jj < 4; jj++) ga[ii][jj] += p * rv[jj];
        }
    }

    #pragma unroll
    for (int ii = 0; ii < 4; ii++) {
        int i = ty * 4 + ii;
        size_t base = (size_t)(b * SLEN + i * SEGLEN + l) * DMODEL + h * DH + tx * 4;
        float4 la = *(const float4*)(g_la + base);
        float cl = s_cl[i], cg = s_cg[i];
        float4 o;
        o.x = cl * la.x + cg * ga[ii][0];
        o.y = cl * la.y + cg * ga[ii][1];
        o.z = cl * la.z + cg * ga[ii][2];
        o.w = cl * la.w + cg * ga[ii][3];
        uint32_t h0, l0, h1, l1, h2, l2, h3, l3;
        hsplit(o.x, h0, l0); hsplit(o.y, h1, l1);
        hsplit(o.z, h2, l2); hsplit(o.w, h3, l3);
        *(uint2*)(g_ah + base) = make_uint2(h0 | (h1 << 16), h2 | (h3 << 16));
        *(uint2*)(g_al + base) = make_uint2(l0 | (l1 << 16), l2 | (l3 << 16));
    }
}

// ---------------------------------------------------------------------------
// LayerNorm: reads kt f32, writes normalized result as fp16 hi/lo split
// ---------------------------------------------------------------------------
__global__ __launch_bounds__(256) void ln_k(const float* __restrict__ x,
                                            const float* __restrict__ sc,
                                            const float* __restrict__ bs,
                                            __half* __restrict__ oh,
                                            __half* __restrict__ ol)
{
    size_t row = blockIdx.x;
    const float* p = x + row * DMODEL;
    int c = threadIdx.x * 4;
    float4 v = *(const float4*)(p + c);
    float s  = v.x + v.y + v.z + v.w;
    float sq = v.x * v.x + v.y * v.y + v.z * v.z + v.w * v.w;
    s  = warp_sum(s);
    sq = warp_sum(sq);
    __shared__ float rs[8], rq[8];
    int warp = threadIdx.x >> 5, lane = threadIdx.x & 31;
    if (lane == 0) { rs[warp] = s; rq[warp] = sq; }
    __syncthreads();
    if (warp == 0) {
        float a = (lane < 8) ? rs[lane] : 0.0f;
        float b = (lane < 8) ? rq[lane] : 0.0f;
        a = warp_sum(a);
        b = warp_sum(b);
        if (lane == 0) { rs[0] = a; rq[0] = b; }
    }
    __syncthreads();
    float mean = rs[0] * (1.0f / DMODEL);
    float var  = rq[0] * (1.0f / DMODEL) - mean * mean;
    float inv  = rsqrtf(var + 1e-6f);
    float4 g = *(const float4*)(sc + c);
    float4 b4 = *(const float4*)(bs + c);
    v.x = (v.x - mean) * inv * g.x + b4.x;
    v.y = (v.y - mean) * inv * g.y + b4.y;
    v.z = (v.z - mean) * inv * g.z + b4.z;
    v.w = (v.w - mean) * inv * g.w + b4.w;
    uint32_t h0, l0, h1, l1, h2, l2, h3, l3;
    hsplit(v.x, h0, l0); hsplit(v.y, h1, l1);
    hsplit(v.z, h2, l2); hsplit(v.w, h3, l3);
    size_t o = row * DMODEL + c;
    *(uint2*)(oh + o) = make_uint2(h0 | (h1 << 16), h2 | (h3 << 16));
    *(uint2*)(ol + o) = make_uint2(l0 | (l1 << 16), l2 | (l3 << 16));
}

// ---------------------------------------------------------------------------
// Host launcher
// ---------------------------------------------------------------------------
extern "C" void kernel_launch(void* const* d_in, const int* in_sizes, int n_in,
                              void* d_out, int out_size)
{
    const float* x    = (const float*)d_in[0];
    const float* Wq   = (const float*)d_in[1];
    const float* Wk   = (const float*)d_in[2];
    const float* Wv   = (const float*)d_in[3];
    const float* Wrow = (const float*)d_in[4];
    const float* lns  = (const float*)d_in[5];
    const float* lnb  = (const float*)d_in[6];
    const float* Wk2  = (const float*)d_in[7];
    const float* Wout = (const float*)d_in[8];
    float* out = (float*)d_out;

    float *qkv, *kt, *k2;
    cudaGetSymbolAddress((void**)&qkv, g_qkv);
    cudaGetSymbolAddress((void**)&kt,  g_kt);
    cudaGetSymbolAddress((void**)&k2,  g_k2);

    __half *w16, *ah, *al;
    cudaGetSymbolAddress((void**)&w16, g_w16);
    cudaGetSymbolAddress((void**)&ah, g_ah);
    cudaGetSymbolAddress((void**)&al, g_al);
    const size_t WSZ = (size_t)DMODEL * DMODEL;
    const size_t MSZ = (size_t)NTOK * DMODEL;

    const int ATT_SMEM = 3 * 64 * PCH * (int)sizeof(float);
    cudaFuncSetAttribute(attn_local_k,  cudaFuncAttributeMaxDynamicSharedMemorySize, ATT_SMEM);
    cudaFuncSetAttribute(attn_global_k, cudaFuncAttributeMaxDynamicSharedMemorySize, ATT_SMEM);
    cudaFuncSetAttribute(gemm_mma, cudaFuncAttributeMaxDynamicSharedMemorySize, GSMEM);

    // weight prep (transpose + fp16; Wq pre-scaled by 1/sqrt(HD)=0.125)
    dim3 wsg(32, 32), wst(256);
    wprep_k<<<wsg, wst>>>(Wq,   w16 + 0 * WSZ, 0.125f);
    wprep_k<<<wsg, wst>>>(Wk,   w16 + 1 * WSZ, 1.0f);
    wprep_k<<<wsg, wst>>>(Wv,   w16 + 2 * WSZ, 1.0f);
    wprep_k<<<wsg, wst>>>(Wrow, w16 + 3 * WSZ, 1.0f);
    wprep_k<<<wsg, wst>>>(Wk2,  w16 + 4 * WSZ, 1.0f);
    wprep_k<<<wsg, wst>>>(Wout, w16 + 5 * WSZ, 1.0f);

    dim3 gq(3 * DMODEL / 128, NTOK / 128);   // fused QKV: (24, 128)
    dim3 gg(DMODEL / 128, NTOK / 128);       // (8, 128)
    dim3 bt(256);
    const int ASPLIT_G = (NTOK * DMODEL) / (256 * 4);

    // x -> hi/lo, then fused QKV projection
    asplit_k<<<ASPLIT_G, 256>>>(x, ah, al);
    gemm_mma<<<gq, bt, GSMEM>>>(ah, al, w16, nullptr, qkv, MSZ);

    // local attention: writes ra f32 + ra split into ah/al
    attn_local_k<<<NBATCH * NSEG * NH, 256, ATT_SMEM>>>();

    gemm_mma<<<gg, bt, GSMEM>>>(ah, al, w16 + 3 * WSZ, x, kt, 0);
    ln_k<<<NTOK, 256>>>(kt, lns, lnb, ah, al);
    gemm_mma<<<gg, bt, GSMEM>>>(ah, al, w16 + 4 * WSZ, nullptr, k2, 0);

    // global attention + merge: writes merged split into ah/al
    attn_global_k<<<NBATCH * SEGLEN * NH, 256, ATT_SMEM>>>();

    gemm_mma<<<gg, bt, GSMEM>>>(ah, al, w16 + 5 * WSZ, nullptr, out, 0);
}

// round 7
// speedup vs baseline: 4.2168x; 1.3760x over previous
#include <cuda_runtime.h>
#include <cuda_fp16.h>
#include <cstdint>

// ---------------------------------------------------------------------------
// Problem constants
// ---------------------------------------------------------------------------
#define NTOK   16384      // B*S
#define DMODEL 1024
#define NH     16
#define DH     64
#define SEGLEN 64
#define NSEG   64
#define SLEN   4096
#define NBATCH 4
#define NEGINF -1e10f

// ---------------------------------------------------------------------------
// Scratch (device globals)
// ---------------------------------------------------------------------------
__device__ float g_qkv[3 * NTOK * DMODEL];   // q | k | v contiguous
__device__ float g_ra[NTOK * DMODEL];
__device__ float g_la[NTOK * DMODEL];
__device__ float g_kt[NTOK * DMODEL];
__device__ float g_k2[NTOK * DMODEL];
__device__ float g_mloc[NTOK * NH];
__device__ float g_sloc[NTOK * NH];

// Pre-transposed fp16 weights: [6][N=1024][K=1024] (Wq pre-scaled by 0.125)
__device__ __half g_w16[6][DMODEL * DMODEL];
// Activation fp16 (producers write this directly)
__device__ __half g_ah[NTOK * DMODEL];

// ---------------------------------------------------------------------------
// Helpers
// ---------------------------------------------------------------------------
__device__ __forceinline__ uint32_t smem_u32(const void* p) {
    uint32_t a;
    asm("{ .reg .u64 t; cvta.to.shared.u64 t, %1; cvt.u32.u64 %0, t; }"
        : "=r"(a) : "l"(p));
    return a;
}
__device__ __forceinline__ void cpasync16(uint32_t s, const void* g) {
    asm volatile("cp.async.cg.shared.global [%0], [%1], 16;" :: "r"(s), "l"(g));
}
#define CP_COMMIT() asm volatile("cp.async.commit_group;")
#define CP_WAIT1()  asm volatile("cp.async.wait_group 1;")
#define CP_WAIT0()  asm volatile("cp.async.wait_group 0;")

#define LDSM4(r0, r1, r2, r3, addr) \
    asm volatile("ldmatrix.sync.aligned.m8n8.x4.shared.b16 {%0,%1,%2,%3}, [%4];" \
                 : "=r"(r0), "=r"(r1), "=r"(r2), "=r"(r3) : "r"(addr))

#define MMA16816(c0, c1, c2, c3, a0, a1, a2, a3, b0, b1) \
    asm volatile("mma.sync.aligned.m16n8k16.row.col.f32.f16.f16.f32 " \
                 "{%0,%1,%2,%3}, {%4,%5,%6,%7}, {%8,%9}, {%0,%1,%2,%3};" \
                 : "+f"(c0), "+f"(c1), "+f"(c2), "+f"(c3) \
                 : "r"(a0), "r"(a1), "r"(a2), "r"(a3), "r"(b0), "r"(b1))

__device__ __forceinline__ uint32_t hb(float v) {
    return (uint32_t)__half_as_ushort(__float2half(v));
}

// ---------------------------------------------------------------------------
// Weight transpose + fp16 convert (with scale):  W[K][N] -> T[N][K] fp16
// ---------------------------------------------------------------------------
__global__ __launch_bounds__(256) void wprep_k(const float* __restrict__ W,
                                               __half* __restrict__ T,
                                               float scale)
{
    __shared__ float t[32][33];
    int bn = blockIdx.x * 32;
    int bk = blockIdx.y * 32;
    int x = threadIdx.x & 31;
    int y = threadIdx.x >> 5;
    #pragma unroll
    for (int i = 0; i < 32; i += 8)
        t[y + i][x] = W[(size_t)(bk + y + i) * DMODEL + bn + x];
    __syncthreads();
    #pragma unroll
    for (int i = 0; i < 32; i += 8) {
        float v = t[x][y + i] * scale;
        T[(size_t)(bn + y + i) * DMODEL + bk + x] = __float2half(v);
    }
}

// ---------------------------------------------------------------------------
// Activation fp32 -> fp16 convert (only used for the input x)
// ---------------------------------------------------------------------------
__global__ __launch_bounds__(256) void aconv_k(const float* __restrict__ in,
                                               __half* __restrict__ oh)
{
    size_t i = ((size_t)blockIdx.x * 256 + threadIdx.x) * 4;
    float4 v = *(const float4*)(in + i);
    *(uint2*)(oh + i) = make_uint2(hb(v.x) | (hb(v.y) << 16),
                                   hb(v.z) | (hb(v.w) << 16));
}

// ---------------------------------------------------------------------------
// Tensor-core GEMM (pure fp16 A and B, fp32 accumulate)
//   Out[tN>>3] tile: C + (tN>>3)*matStride, cols (tN&7)*128 ..
//   CTA tile 128x128, BK=32, 3-stage cp.async pipeline (1 barrier/chunk).
// ---------------------------------------------------------------------------
#define GBK    32
#define GPITCH 40                      // fp16 elements per smem row (80 B)
#define GTILE_B (128 * GPITCH * 2)     // 10240 B per tile
#define GSTAGE_B (2 * GTILE_B)         // A, B = 20480 B
#define GSMEM   (3 * GSTAGE_B)         // 3 stages = 61440 B

__global__ __launch_bounds__(256) void gemm_mma(
    const __half* __restrict__ Ah,
    const __half* __restrict__ Bf,
    const float* __restrict__ res, float* __restrict__ C, size_t matStride)
{
    extern __shared__ char dsm[];
    const uint32_t sb = smem_u32(dsm);

    const int tid  = threadIdx.x;
    const int wid  = tid >> 5;
    const int lane = tid & 31;
    const int tM = blockIdx.y, tN = blockIdx.x;
    const int wm = wid & 1;        // 2 warp-rows (64 M each)
    const int wn = wid >> 1;       // 4 warp-cols (32 N each)

    const int r0 = tid >> 2;              // 0..63
    const int c0 = (tid & 3);             // 16B chunk col 0..3

    const __half* Ahp = Ah + (size_t)(tM * 128) * DMODEL;
    const __half* Bp  = Bf + (size_t)(tN * 128) * DMODEL;

    float acc[4][4][4];
    #pragma unroll
    for (int i = 0; i < 4; i++)
        #pragma unroll
        for (int j = 0; j < 4; j++)
            #pragma unroll
            for (int t = 0; t < 4; t++) acc[i][j][t] = 0.0f;

    auto issue_chunk = [&](int c, int st) {
        const int k0 = c * GBK;
        uint32_t s = sb + st * GSTAGE_B;
        #pragma unroll
        for (int half = 0; half < 2; half++) {
            int r = r0 + half * 64;
            uint32_t so = (uint32_t)(r * (GPITCH * 2) + c0 * 16);
            size_t go = (size_t)r * DMODEL + k0 + c0 * 8;
            cpasync16(s + 0 * GTILE_B + so, Ahp + go);
            cpasync16(s + 1 * GTILE_B + so, Bp  + go);
        }
        CP_COMMIT();
    };

    issue_chunk(0, 0);
    issue_chunk(1, 1);

    const int NC = DMODEL / GBK;   // 32
    for (int c = 0; c < NC; c++) {
        const int st = c % 3;
        if (c + 1 < NC) CP_WAIT1(); else CP_WAIT0();
        __syncthreads();
        if (c + 2 < NC) issue_chunk(c + 2, (c + 2) % 3);

        uint32_t sA = sb + st * GSTAGE_B;
        uint32_t sB = sA + GTILE_B;

        const int a_row = (lane & 15);
        const int a_kh  = (lane >> 4) * 8;
        const int b_row = (lane & 7) + ((lane >> 4) << 3);
        const int b_kh  = ((lane >> 3) & 1) * 8;

        #pragma unroll
        for (int ks = 0; ks < 2; ks++) {
            const int kb = ks * 16;
            uint32_t aa[4][4], bb[4][2];
            #pragma unroll
            for (int mt = 0; mt < 4; mt++) {
                uint32_t off = (uint32_t)((wm * 64 + mt * 16 + a_row) * (GPITCH * 2)
                                          + (kb + a_kh) * 2);
                LDSM4(aa[mt][0], aa[mt][1], aa[mt][2], aa[mt][3], sA + off);
            }
            #pragma unroll
            for (int j = 0; j < 2; j++) {
                uint32_t off = (uint32_t)((wn * 32 + j * 16 + b_row) * (GPITCH * 2)
                                          + (kb + b_kh) * 2);
                LDSM4(bb[2*j][0], bb[2*j][1], bb[2*j+1][0], bb[2*j+1][1], sB + off);
            }
            #pragma unroll
            for (int mt = 0; mt < 4; mt++)
                #pragma unroll
                for (int nt = 0; nt < 4; nt++)
                    MMA16816(acc[mt][nt][0], acc[mt][nt][1], acc[mt][nt][2], acc[mt][nt][3],
                             aa[mt][0], aa[mt][1], aa[mt][2], aa[mt][3],
                             bb[nt][0], bb[nt][1]);
        }
    }

    // Epilogue
    float* Cb = C + (size_t)(tN >> 3) * matStride;
    const int colb = (tN & 7) * 128;
    #pragma unroll
    for (int mt = 0; mt < 4; mt++) {
        #pragma unroll
        for (int nt = 0; nt < 4; nt++) {
            int row = tM * 128 + wm * 64 + mt * 16 + (lane >> 2);
            int col = colb + wn * 32 + nt * 8 + (lane & 3) * 2;
            #pragma unroll
            for (int hh = 0; hh < 2; hh++) {
                size_t o = (size_t)(row + hh * 8) * DMODEL + col;
                float2 v;
                v.x = acc[mt][nt][hh * 2 + 0];
                v.y = acc[mt][nt][hh * 2 + 1];
                if (res) {
                    float2 rr = *(const float2*)(res + o);
                    v.x += rr.x; v.y += rr.y;
                }
                *(float2*)(Cb + o) = v;
            }
        }
    }
}

// ---------------------------------------------------------------------------
// Warp utils
// ---------------------------------------------------------------------------
__device__ __forceinline__ float warp_max(float v) {
    #pragma unroll
    for (int o = 16; o > 0; o >>= 1) v = fmaxf(v, __shfl_xor_sync(0xffffffffu, v, o));
    return v;
}
__device__ __forceinline__ float warp_sum(float v) {
    #pragma unroll
    for (int o = 16; o > 0; o >>= 1) v += __shfl_xor_sync(0xffffffffu, v, o);
    return v;
}

#define PCH 65  // smem pitch (64 + 1 pad)

// ---------------------------------------------------------------------------
// Local attention: one block per (b, seg, h).
// Writes: g_ra f32 + g_ah fp16(ra), g_la f32, g_mloc, g_sloc
// ---------------------------------------------------------------------------
__global__ __launch_bounds__(256, 4) void attn_local_k()
{
    extern __shared__ float sm[];
    float* sq = sm;
    float* sk = sm + 64 * PCH;
    float* sv = sm + 2 * 64 * PCH;

    const float* g_q = g_qkv;
    const float* g_k = g_qkv + (size_t)NTOK * DMODEL;
    const float* g_v = g_qkv + 2 * (size_t)NTOK * DMODEL;

    int bid = blockIdx.x;
    int h   = bid % NH;
    int seg = (bid / NH) % NSEG;
    int b   = bid / (NH * NSEG);
    int t0  = b * SLEN + seg * SEGLEN;
    int tid = threadIdx.x;

    for (int idx = tid; idx < 1024; idx += 256) {
        int r = idx >> 4;
        int c = (idx & 15) << 2;
        size_t g = (size_t)(t0 + r) * DMODEL + h * DH + c;
        float4 a = *(const float4*)(g_q + g);
        sq[r * PCH + c] = a.x; sq[r * PCH + c + 1] = a.y;
        sq[r * PCH + c + 2] = a.z; sq[r * PCH + c + 3] = a.w;
        float4 bb = *(const float4*)(g_k + g);
        sk[r * PCH + c] = bb.x; sk[r * PCH + c + 1] = bb.y;
        sk[r * PCH + c + 2] = bb.z; sk[r * PCH + c + 3] = bb.w;
        float4 vv = *(const float4*)(g_v + g);
        sv[r * PCH + c] = vv.x; sv[r * PCH + c + 1] = vv.y;
        sv[r * PCH + c + 2] = vv.z; sv[r * PCH + c + 3] = vv.w;
    }
    __syncthreads();

    int tx = tid & 15, ty = tid >> 4;
    float acc[4][4];
    #pragma unroll
    for (int i = 0; i < 4; i++)
        #pragma unroll
        for (int j = 0; j < 4; j++) acc[i][j] = 0.0f;

    for (int d = 0; d < 64; d++) {
        float qa[4], kb[4];
        #pragma unroll
        for (int i = 0; i < 4; i++) qa[i] = sq[(ty * 4 + i) * PCH + d];
        #pragma unroll
        for (int j = 0; j < 4; j++) kb[j] = sk[(tx * 4 + j) * PCH + d];
        #pragma unroll
        for (int i = 0; i < 4; i++)
            #pragma unroll
            for (int j = 0; j < 4; j++) acc[i][j] += qa[i] * kb[j];
    }
    __syncthreads();

    #pragma unroll
    for (int i = 0; i < 4; i++)
        #pragma unroll
        for (int j = 0; j < 4; j++)
            sq[(ty * 4 + i) * PCH + tx * 4 + j] = acc[i][j];
    __syncthreads();

    int warp = tid >> 5, lane = tid & 31;
    for (int r = warp; r < 64; r += 8) {
        float l0 = sq[r * PCH + lane];
        float l1 = sq[r * PCH + 32 + lane];
        float mx = warp_max(fmaxf(l0, l1));
        float k0 = (lane <= r)      ? l0 : -3e38f;
        float k1 = (lane + 32 <= r) ? l1 : -3e38f;
        float mm = warp_max(fmaxf(k0, k1));
        float e0 = __expf(l0 - mx), e1 = __expf(l1 - mx);
        float su = warp_sum(e0 + e1);
        float em0 = (lane <= r)      ? __expf(l0 - mm) : 0.0f;
        float em1 = (lane + 32 <= r) ? __expf(l1 - mm) : 0.0f;
        float ss = warp_sum(em0 + em1);
        float inv = 1.0f / su;
        sq[r * PCH + lane]      = e0 * inv;
        sq[r * PCH + 32 + lane] = e1 * inv;
        sk[r * PCH + lane]      = em0;
        sk[r * PCH + 32 + lane] = em1;
        if (lane == 0) {
            g_mloc[(t0 + r) * NH + h] = mm;
            g_sloc[(t0 + r) * NH + h] = ss;
        }
    }
    __syncthreads();

    float a1[4][4], a2[4][4];
    #pragma unroll
    for (int i = 0; i < 4; i++)
        #pragma unroll
        for (int j = 0; j < 4; j++) { a1[i][j] = 0.0f; a2[i][j] = 0.0f; }

    for (int j = 0; j < 64; j++) {
        float vv[4];
        #pragma unroll
        for (int jj = 0; jj < 4; jj++) vv[jj] = sv[j * PCH + tx * 4 + jj];
        #pragma unroll
        for (int ii = 0; ii < 4; ii++) {
            float pu = sq[(ty * 4 + ii) * PCH + j];
            float pm = sk[(ty * 4 + ii) * PCH + j];
            #pragma unroll
            for (int jj = 0; jj < 4; jj++) {
                a1[ii][jj] += pu * vv[jj];
                a2[ii][jj] += pm * vv[jj];
            }
        }
    }

    #pragma unroll
    for (int ii = 0; ii < 4; ii++) {
        size_t base = (size_t)(t0 + ty * 4 + ii) * DMODEL + h * DH + tx * 4;
        float4 o1 = {a1[ii][0], a1[ii][1], a1[ii][2], a1[ii][3]};
        float4 o2 = {a2[ii][0], a2[ii][1], a2[ii][2], a2[ii][3]};
        *(float4*)(g_ra + base) = o1;
        *(float4*)(g_la + base) = o2;
        *(uint2*)(g_ah + base) = make_uint2(hb(o1.x) | (hb(o1.y) << 16),
                                            hb(o1.z) | (hb(o1.w) << 16));
    }
}

// ---------------------------------------------------------------------------
// Global attention + merge: one block per (b, l, h).
// Writes merged directly as fp16 (g_ah).
// ---------------------------------------------------------------------------
__global__ __launch_bounds__(256, 4) void attn_global_k()
{
    extern __shared__ float sm[];
    float* sq = sm;
    float* sk = sm + 64 * PCH;
    float* sr = sm + 2 * 64 * PCH;
    __shared__ float s_cl[64], s_cg[64];

    const float* g_q = g_qkv;

    int bid = blockIdx.x;
    int h   = bid % NH;
    int l   = (bid / NH) % SEGLEN;
    int b   = bid / (NH * SEGLEN);
    int tid = threadIdx.x;

    for (int idx = tid; idx < 1024; idx += 256) {
        int r = idx >> 4;
        int c = (idx & 15) << 2;
        size_t g = (size_t)(b * SLEN + r * SEGLEN + l) * DMODEL + h * DH + c;
        float4 a = *(const float4*)(g_q + g);
        sq[r * PCH + c] = a.x; sq[r * PCH + c + 1] = a.y;
        sq[r * PCH + c + 2] = a.z; sq[r * PCH + c + 3] = a.w;
        float4 kk = *(const float4*)(g_k2 + g);
        sk[r * PCH + c] = kk.x; sk[r * PCH + c + 1] = kk.y;
        sk[r * PCH + c + 2] = kk.z; sk[r * PCH + c + 3] = kk.w;
        float4 rr = *(const float4*)(g_ra + g);
        sr[r * PCH + c] = rr.x; sr[r * PCH + c + 1] = rr.y;
        sr[r * PCH + c + 2] = rr.z; sr[r * PCH + c + 3] = rr.w;
    }
    __syncthreads();

    int tx = tid & 15, ty = tid >> 4;
    float acc[4][4];
    #pragma unroll
    for (int i = 0; i < 4; i++)
        #pragma unroll
        for (int j = 0; j < 4; j++) acc[i][j] = 0.0f;

    for (int d = 0; d < 64; d++) {
        float qa[4], kb[4];
        #pragma unroll
        for (int i = 0; i < 4; i++) qa[i] = sq[(ty * 4 + i) * PCH + d];
        #pragma unroll
        for (int j = 0; j < 4; j++) kb[j] = sk[(tx * 4 + j) * PCH + d];
        #pragma unroll
        for (int i = 0; i < 4; i++)
            #pragma unroll
            for (int j = 0; j < 4; j++) acc[i][j] += qa[i] * kb[j];
    }
    __syncthreads();

    #pragma unroll
    for (int ii = 0; ii < 4; ii++)
        #pragma unroll
        for (int jj = 0; jj < 4; jj++) {
            int i = ty * 4 + ii, j = tx * 4 + jj;
            sq[i * PCH + j] = acc[ii][jj] + ((j >= i) ? NEGINF : 0.0f);
        }
    __syncthreads();

    int warp = tid >> 5, lane = tid & 31;
    for (int r = warp; r < 64; r += 8) {
        float l0 = sq[r * PCH + lane];
        float l1 = sq[r * PCH + 32 + lane];
        float mg = warp_max(fmaxf(l0, l1));
        float e0 = __expf(l0 - mg), e1 = __expf(l1 - mg);
        float sg = warp_sum(e0 + e1);
        sq[r * PCH + lane]      = e0;
        sq[r * PCH + 32 + lane] = e1;
        if (lane == 0) {
            int t = b * SLEN + r * SEGLEN + l;
            float mlc = g_mloc[t * NH + h];
            float slc = g_sloc[t * NH + h];
            float m  = fmaxf(mlc, mg);
            float al = __expf(mlc - m);
            float ag = __expf(mg - m);
            float inv = 1.0f / (slc * al + sg * ag);
            s_cl[r] = al * inv;
            s_cg[r] = ag * inv;
        }
    }
    __syncthreads();

    float ga[4][4];
    #pragma unroll
    for (int i = 0; i < 4; i++)
        #pragma unroll
        for (int j = 0; j < 4; j++) ga[i][j] = 0.0f;

    for (int j = 0; j < 64; j++) {
        float rv[4];
        #pragma unroll
        for (int jj = 0; jj < 4; jj++) rv[jj] = sr[j * PCH + tx * 4 + jj];
        #pragma unroll
        for (int ii = 0; ii < 4; ii++) {
            float p = sq[(ty * 4 + ii) * PCH + j];
            #pragma unroll
            for (int jj = 0; jj < 4; jj++) ga[ii][jj] += p * rv[jj];
        }
    }

    #pragma unroll
    for (int ii = 0; ii < 4; ii++) {
        int i = ty * 4 + ii;
        size_t base = (size_t)(b * SLEN + i * SEGLEN + l) * DMODEL + h * DH + tx * 4;
        float4 la = *(const float4*)(g_la + base);
        float cl = s_cl[i], cg = s_cg[i];
        float4 o;
        o.x = cl * la.x + cg * ga[ii][0];
        o.y = cl * la.y + cg * ga[ii][1];
        o.z = cl * la.z + cg * ga[ii][2];
        o.w = cl * la.w + cg * ga[ii][3];
        *(uint2*)(g_ah + base) = make_uint2(hb(o.x) | (hb(o.y) << 16),
                                            hb(o.z) | (hb(o.w) << 16));
    }
}

// ---------------------------------------------------------------------------
// LayerNorm: reads kt f32, writes normalized result as fp16
// ---------------------------------------------------------------------------
__global__ __launch_bounds__(256) void ln_k(const float* __restrict__ x,
                                            const float* __restrict__ sc,
                                            const float* __restrict__ bs,
                                            __half* __restrict__ oh)
{
    size_t row = blockIdx.x;
    const float* p = x + row * DMODEL;
    int c = threadIdx.x * 4;
    float4 v = *(const float4*)(p + c);
    float s  = v.x + v.y + v.z + v.w;
    float sq = v.x * v.x + v.y * v.y + v.z * v.z + v.w * v.w;
    s  = warp_sum(s);
    sq = warp_sum(sq);
    __shared__ float rs[8], rq[8];
    int warp = threadIdx.x >> 5, lane = threadIdx.x & 31;
    if (lane == 0) { rs[warp] = s; rq[warp] = sq; }
    __syncthreads();
    if (warp == 0) {
        float a = (lane < 8) ? rs[lane] : 0.0f;
        float b = (lane < 8) ? rq[lane] : 0.0f;
        a = warp_sum(a);
        b = warp_sum(b);
        if (lane == 0) { rs[0] = a; rq[0] = b; }
    }
    __syncthreads();
    float mean = rs[0] * (1.0f / DMODEL);
    float var  = rq[0] * (1.0f / DMODEL) - mean * mean;
    float inv  = rsqrtf(var + 1e-6f);
    float4 g = *(const float4*)(sc + c);
    float4 b4 = *(const float4*)(bs + c);
    v.x = (v.x - mean) * inv * g.x + b4.x;
    v.y = (v.y - mean) * inv * g.y + b4.y;
    v.z = (v.z - mean) * inv * g.z + b4.z;
    v.w = (v.w - mean) * inv * g.w + b4.w;
    size_t o = row * DMODEL + c;
    *(uint2*)(oh + o) = make_uint2(hb(v.x) | (hb(v.y) << 16),
                                   hb(v.z) | (hb(v.w) << 16));
}

// ---------------------------------------------------------------------------
// Host launcher
// ---------------------------------------------------------------------------
extern "C" void kernel_launch(void* const* d_in, const int* in_sizes, int n_in,
                              void* d_out, int out_size)
{
    const float* x    = (const float*)d_in[0];
    const float* Wq   = (const float*)d_in[1];
    const float* Wk   = (const float*)d_in[2];
    const float* Wv   = (const float*)d_in[3];
    const float* Wrow = (const float*)d_in[4];
    const float* lns  = (const float*)d_in[5];
    const float* lnb  = (const float*)d_in[6];
    const float* Wk2  = (const float*)d_in[7];
    const float* Wout = (const float*)d_in[8];
    float* out = (float*)d_out;

    float *qkv, *kt, *k2;
    cudaGetSymbolAddress((void**)&qkv, g_qkv);
    cudaGetSymbolAddress((void**)&kt,  g_kt);
    cudaGetSymbolAddress((void**)&k2,  g_k2);

    __half *w16, *ah;
    cudaGetSymbolAddress((void**)&w16, g_w16);
    cudaGetSymbolAddress((void**)&ah, g_ah);
    const size_t WSZ = (size_t)DMODEL * DMODEL;
    const size_t MSZ = (size_t)NTOK * DMODEL;

    const int ATT_SMEM = 3 * 64 * PCH * (int)sizeof(float);
    cudaFuncSetAttribute(attn_local_k,  cudaFuncAttributeMaxDynamicSharedMemorySize, ATT_SMEM);
    cudaFuncSetAttribute(attn_global_k, cudaFuncAttributeMaxDynamicSharedMemorySize, ATT_SMEM);
    cudaFuncSetAttribute(gemm_mma, cudaFuncAttributeMaxDynamicSharedMemorySize, GSMEM);

    // weight prep (transpose + fp16; Wq pre-scaled by 1/sqrt(HD)=0.125)
    dim3 wsg(32, 32), wst(256);
    wprep_k<<<wsg, wst>>>(Wq,   w16 + 0 * WSZ, 0.125f);
    wprep_k<<<wsg, wst>>>(Wk,   w16 + 1 * WSZ, 1.0f);
    wprep_k<<<wsg, wst>>>(Wv,   w16 + 2 * WSZ, 1.0f);
    wprep_k<<<wsg, wst>>>(Wrow, w16 + 3 * WSZ, 1.0f);
    wprep_k<<<wsg, wst>>>(Wk2,  w16 + 4 * WSZ, 1.0f);
    wprep_k<<<wsg, wst>>>(Wout, w16 + 5 * WSZ, 1.0f);

    dim3 gq(3 * DMODEL / 128, NTOK / 128);   // fused QKV: (24, 128)
    dim3 gg(DMODEL / 128, NTOK / 128);       // (8, 128)
    dim3 bt(256);
    const int ACONV_G = (NTOK * DMODEL) / (256 * 4);

    // x -> fp16, then fused QKV projection
    aconv_k<<<ACONV_G, 256>>>(x, ah);
    gemm_mma<<<gq, bt, GSMEM>>>(ah, w16, nullptr, qkv, MSZ);

    // local attention: writes ra f32 + ra fp16 into ah
    attn_local_k<<<NBATCH * NSEG * NH, 256, ATT_SMEM>>>();

    gemm_mma<<<gg, bt, GSMEM>>>(ah, w16 + 3 * WSZ, x, kt, 0);
    ln_k<<<NTOK, 256>>>(kt, lns, lnb, ah);
    gemm_mma<<<gg, bt, GSMEM>>>(ah, w16 + 4 * WSZ, nullptr, k2, 0);

    // global attention + merge: writes merged fp16 into ah
    attn_global_k<<<NBATCH * SEGLEN * NH, 256, ATT_SMEM>>>();

    gemm_mma<<<gg, bt, GSMEM>>>(ah, w16 + 5 * WSZ, nullptr, out, 0);
}

// round 8
// speedup vs baseline: 4.9137x; 1.1653x over previous
#include <cuda_runtime.h>
#include <cuda_fp16.h>
#include <cstdint>

// ---------------------------------------------------------------------------
// Problem constants
// ---------------------------------------------------------------------------
#define NTOK   16384      // B*S
#define DMODEL 1024
#define NH     16
#define DH     64
#define SEGLEN 64
#define NSEG   64
#define SLEN   4096
#define NBATCH 4
#define NEGINF -1e10f

// ---------------------------------------------------------------------------
// Scratch (device globals)
// ---------------------------------------------------------------------------
__device__ __half g_qkvh[3 * NTOK * DMODEL];  // q | k | v fp16
__device__ __half g_rah [NTOK * DMODEL];      // row_attn fp16 (GEMM A + attn_global B)
__device__ __half g_k2h [NTOK * DMODEL];      // key_row2 fp16
__device__ __half g_ah  [NTOK * DMODEL];      // generic fp16 activation (x, ln-out, merged)
__device__ float  g_kt  [NTOK * DMODEL];      // key_row f32 (pre-LN)
__device__ float  g_la  [NTOK * DMODEL];      // unnormalized masked-local P@V (f32)
__device__ float  g_mloc[NTOK * NH];
__device__ float  g_sloc[NTOK * NH];

// Pre-transposed fp16 weights: [6][N=1024][K=1024] (Wq pre-scaled by 0.125)
__device__ __half g_w16[6][DMODEL * DMODEL];

// ---------------------------------------------------------------------------
// Helpers
// ---------------------------------------------------------------------------
__device__ __forceinline__ uint32_t smem_u32(const void* p) {
    uint32_t a;
    asm("{ .reg .u64 t; cvta.to.shared.u64 t, %1; cvt.u32.u64 %0, t; }"
        : "=r"(a) : "l"(p));
    return a;
}
__device__ __forceinline__ void cpasync16(uint32_t s, const void* g) {
    asm volatile("cp.async.cg.shared.global [%0], [%1], 16;" :: "r"(s), "l"(g));
}
#define CP_COMMIT() asm volatile("cp.async.commit_group;")
#define CP_WAIT1()  asm volatile("cp.async.wait_group 1;")
#define CP_WAIT0()  asm volatile("cp.async.wait_group 0;")

#define LDSM4(r0, r1, r2, r3, addr) \
    asm volatile("ldmatrix.sync.aligned.m8n8.x4.shared.b16 {%0,%1,%2,%3}, [%4];" \
                 : "=r"(r0), "=r"(r1), "=r"(r2), "=r"(r3) : "r"(addr))
#define LDSM4T(r0, r1, r2, r3, addr) \
    asm volatile("ldmatrix.sync.aligned.m8n8.x4.trans.shared.b16 {%0,%1,%2,%3}, [%4];" \
                 : "=r"(r0), "=r"(r1), "=r"(r2), "=r"(r3) : "r"(addr))

#define MMA16816(c0, c1, c2, c3, a0, a1, a2, a3, b0, b1) \
    asm volatile("mma.sync.aligned.m16n8k16.row.col.f32.f16.f16.f32 " \
                 "{%0,%1,%2,%3}, {%4,%5,%6,%7}, {%8,%9}, {%0,%1,%2,%3};" \
                 : "+f"(c0), "+f"(c1), "+f"(c2), "+f"(c3) \
                 : "r"(a0), "r"(a1), "r"(a2), "r"(a3), "r"(b0), "r"(b1))

__device__ __forceinline__ uint32_t hb(float v) {
    return (uint32_t)__half_as_ushort(__float2half(v));
}

// ---------------------------------------------------------------------------
// Weight transpose + fp16 convert (with scale):  W[K][N] -> T[N][K] fp16
// ---------------------------------------------------------------------------
__global__ __launch_bounds__(256) void wprep_k(const float* __restrict__ W,
                                               __half* __restrict__ T,
                                               float scale)
{
    __shared__ float t[32][33];
    int bn = blockIdx.x * 32;
    int bk = blockIdx.y * 32;
    int x = threadIdx.x & 31;
    int y = threadIdx.x >> 5;
    #pragma unroll
    for (int i = 0; i < 32; i += 8)
        t[y + i][x] = W[(size_t)(bk + y + i) * DMODEL + bn + x];
    __syncthreads();
    #pragma unroll
    for (int i = 0; i < 32; i += 8) {
        float v = t[x][y + i] * scale;
        T[(size_t)(bn + y + i) * DMODEL + bk + x] = __float2half(v);
    }
}

// ---------------------------------------------------------------------------
// Activation fp32 -> fp16 convert (only used for the input x)
// ---------------------------------------------------------------------------
__global__ __launch_bounds__(256) void aconv_k(const float* __restrict__ in,
                                               __half* __restrict__ oh)
{
    size_t i = ((size_t)blockIdx.x * 256 + threadIdx.x) * 4;
    float4 v = *(const float4*)(in + i);
    *(uint2*)(oh + i) = make_uint2(hb(v.x) | (hb(v.y) << 16),
                                   hb(v.z) | (hb(v.w) << 16));
}

// ---------------------------------------------------------------------------
// Tensor-core GEMM (pure fp16, fp32 accumulate). HALF_OUT selects C dtype.
// ---------------------------------------------------------------------------
#define GBK    32
#define GPITCH 40                      // fp16 elements per smem row (80 B)
#define GTILE_B (128 * GPITCH * 2)     // 10240 B per tile
#define GSTAGE_B (2 * GTILE_B)         // A, B = 20480 B
#define GSMEM   (3 * GSTAGE_B)         // 3 stages = 61440 B

template<bool HALF_OUT>
__global__ __launch_bounds__(256) void gemm_mma(
    const __half* __restrict__ Ah,
    const __half* __restrict__ Bf,
    const float* __restrict__ res, void* __restrict__ Cv, size_t matStride)
{
    extern __shared__ char dsm[];
    const uint32_t sb = smem_u32(dsm);

    const int tid  = threadIdx.x;
    const int wid  = tid >> 5;
    const int lane = tid & 31;
    const int tM = blockIdx.y, tN = blockIdx.x;
    const int wm = wid & 1;
    const int wn = wid >> 1;

    const int r0 = tid >> 2;
    const int c0 = (tid & 3);

    const __half* Ahp = Ah + (size_t)(tM * 128) * DMODEL;
    const __half* Bp  = Bf + (size_t)(tN * 128) * DMODEL;

    float acc[4][4][4];
    #pragma unroll
    for (int i = 0; i < 4; i++)
        #pragma unroll
        for (int j = 0; j < 4; j++)
            #pragma unroll
            for (int t = 0; t < 4; t++) acc[i][j][t] = 0.0f;

    auto issue_chunk = [&](int c, int st) {
        const int k0 = c * GBK;
        uint32_t s = sb + st * GSTAGE_B;
        #pragma unroll
        for (int half = 0; half < 2; half++) {
            int r = r0 + half * 64;
            uint32_t so = (uint32_t)(r * (GPITCH * 2) + c0 * 16);
            size_t go = (size_t)r * DMODEL + k0 + c0 * 8;
            cpasync16(s + 0 * GTILE_B + so, Ahp + go);
            cpasync16(s + 1 * GTILE_B + so, Bp  + go);
        }
        CP_COMMIT();
    };

    issue_chunk(0, 0);
    issue_chunk(1, 1);

    const int NC = DMODEL / GBK;   // 32
    for (int c = 0; c < NC; c++) {
        const int st = c % 3;
        if (c + 1 < NC) CP_WAIT1(); else CP_WAIT0();
        __syncthreads();
        if (c + 2 < NC) issue_chunk(c + 2, (c + 2) % 3);

        uint32_t sA = sb + st * GSTAGE_B;
        uint32_t sB = sA + GTILE_B;

        const int a_row = (lane & 15);
        const int a_kh  = (lane >> 4) * 8;
        const int b_row = (lane & 7) + ((lane >> 4) << 3);
        const int b_kh  = ((lane >> 3) & 1) * 8;

        #pragma unroll
        for (int ks = 0; ks < 2; ks++) {
            const int kb = ks * 16;
            uint32_t aa[4][4], bb[4][2];
            #pragma unroll
            for (int mt = 0; mt < 4; mt++) {
                uint32_t off = (uint32_t)((wm * 64 + mt * 16 + a_row) * (GPITCH * 2)
                                          + (kb + a_kh) * 2);
                LDSM4(aa[mt][0], aa[mt][1], aa[mt][2], aa[mt][3], sA + off);
            }
            #pragma unroll
            for (int j = 0; j < 2; j++) {
                uint32_t off = (uint32_t)((wn * 32 + j * 16 + b_row) * (GPITCH * 2)
                                          + (kb + b_kh) * 2);
                LDSM4(bb[2*j][0], bb[2*j][1], bb[2*j+1][0], bb[2*j+1][1], sB + off);
            }
            #pragma unroll
            for (int mt = 0; mt < 4; mt++)
                #pragma unroll
                for (int nt = 0; nt < 4; nt++)
                    MMA16816(acc[mt][nt][0], acc[mt][nt][1], acc[mt][nt][2], acc[mt][nt][3],
                             aa[mt][0], aa[mt][1], aa[mt][2], aa[mt][3],
                             bb[nt][0], bb[nt][1]);
        }
    }

    // Epilogue
    const int colb = (tN & 7) * 128;
    #pragma unroll
    for (int mt = 0; mt < 4; mt++) {
        #pragma unroll
        for (int nt = 0; nt < 4; nt++) {
            int row = tM * 128 + wm * 64 + mt * 16 + (lane >> 2);
            int col = colb + wn * 32 + nt * 8 + (lane & 3) * 2;
            #pragma unroll
            for (int hh = 0; hh < 2; hh++) {
                size_t o = (size_t)(row + hh * 8) * DMODEL + col;
                float vx = acc[mt][nt][hh * 2 + 0];
                float vy = acc[mt][nt][hh * 2 + 1];
                if (HALF_OUT) {
                    __half* Cb = (__half*)Cv + (size_t)(tN >> 3) * matStride;
                    *(__half2*)(Cb + o) = __floats2half2_rn(vx, vy);
                } else {
                    float* Cb = (float*)Cv + (size_t)(tN >> 3) * matStride;
                    if (res) {
                        float2 rr = *(const float2*)(res + o);
                        vx += rr.x; vy += rr.y;
                    }
                    *(float2*)(Cb + o) = make_float2(vx, vy);
                }
            }
        }
    }
}

// ---------------------------------------------------------------------------
// Warp utils
// ---------------------------------------------------------------------------
__device__ __forceinline__ float warp_max(float v) {
    #pragma unroll
    for (int o = 16; o > 0; o >>= 1) v = fmaxf(v, __shfl_xor_sync(0xffffffffu, v, o));
    return v;
}
__device__ __forceinline__ float warp_sum(float v) {
    #pragma unroll
    for (int o = 16; o > 0; o >>= 1) v += __shfl_xor_sync(0xffffffffu, v, o);
    return v;
}

// ---------------------------------------------------------------------------
// Attention smem layout (dynamic, 46080 B):
//   [0, 18432)      region A: qh (0, 9216) | kh (9216)  -> later logits f32 (pitch 65)
//   [18432, 27648)  vh (V tile or RA tile)
//   [27648, 36864)  ph (probs fp16)
//   [36864, 46080)  mh (masked-exp fp16; unused by global)
// ---------------------------------------------------------------------------
#define HPI 72           // half pitch (144 B rows, 16B aligned)
#define FPI 65           // f32 pitch for logits
#define ATT_SMEM 46080

// ---------------------------------------------------------------------------
// Local attention: one block per (b, seg, h). mma.sync everywhere.
// ---------------------------------------------------------------------------
__global__ __launch_bounds__(256, 3) void attn_local_k()
{
    extern __shared__ char smraw[];
    __half* qh = (__half*)smraw;
    __half* kh = (__half*)(smraw + 9216);
    float*  lg = (float*)smraw;
    __half* vh = (__half*)(smraw + 18432);
    __half* ph = (__half*)(smraw + 27648);
    __half* mh = (__half*)(smraw + 36864);

    const __half* gq = g_qkvh;
    const __half* gk = g_qkvh + (size_t)NTOK * DMODEL;
    const __half* gv = g_qkvh + 2 * (size_t)NTOK * DMODEL;

    int bid = blockIdx.x;
    int h   = bid % NH;
    int seg = (bid / NH) % NSEG;
    int b   = bid / (NH * NSEG);
    int t0  = b * SLEN + seg * SEGLEN;
    int tid = threadIdx.x;
    const int wid = tid >> 5, lane = tid & 31;
    const int wm = wid >> 1, wn = wid & 1;

    // P0: load q, k, v fp16 tiles
    for (int i = tid; i < 512; i += 256) {
        int r = i >> 3, c = (i & 7) * 8;
        size_t g = (size_t)(t0 + r) * DMODEL + h * DH + c;
        *(uint4*)&qh[r * HPI + c] = *(const uint4*)&gq[g];
        *(uint4*)&kh[r * HPI + c] = *(const uint4*)&gk[g];
        *(uint4*)&vh[r * HPI + c] = *(const uint4*)&gv[g];
    }
    __syncthreads();

    const int a_row = lane & 15, a_kh = (lane >> 4) * 8;
    const int b_row = (lane & 7) + ((lane >> 4) << 3), b_kh = ((lane >> 3) & 1) * 8;

    // P1: logits = Q @ K^T  (warp: rows wm*16.., cols wn*32..)
    float lc[4][4];
    #pragma unroll
    for (int nt = 0; nt < 4; nt++)
        #pragma unroll
        for (int t = 0; t < 4; t++) lc[nt][t] = 0.0f;
    #pragma unroll
    for (int ks = 0; ks < 4; ks++) {
        uint32_t aa[4], bbf[4][2];
        LDSM4(aa[0], aa[1], aa[2], aa[3],
              smem_u32(&qh[(wm * 16 + a_row) * HPI + ks * 16 + a_kh]));
        #pragma unroll
        for (int j = 0; j < 2; j++)
            LDSM4(bbf[2*j][0], bbf[2*j][1], bbf[2*j+1][0], bbf[2*j+1][1],
                  smem_u32(&kh[(wn * 32 + j * 16 + b_row) * HPI + ks * 16 + b_kh]));
        #pragma unroll
        for (int nt = 0; nt < 4; nt++)
            MMA16816(lc[nt][0], lc[nt][1], lc[nt][2], lc[nt][3],
                     aa[0], aa[1], aa[2], aa[3], bbf[nt][0], bbf[nt][1]);
    }
    __syncthreads();   // all reads of qh/kh done before overwrite

    {
        int crow = wm * 16 + (lane >> 2);
        int ccol = wn * 32 + (lane & 3) * 2;
        #pragma unroll
        for (int nt = 0; nt < 4; nt++) {
            lg[crow * FPI + ccol + nt * 8]           = lc[nt][0];
            lg[crow * FPI + ccol + nt * 8 + 1]       = lc[nt][1];
            lg[(crow + 8) * FPI + ccol + nt * 8]     = lc[nt][2];
            lg[(crow + 8) * FPI + ccol + nt * 8 + 1] = lc[nt][3];
        }
    }
    __syncthreads();

    // P2: dual softmax (unmasked probs -> ph, masked exp -> mh)
    for (int r = wid; r < 64; r += 8) {
        float l0 = lg[r * FPI + lane];
        float l1 = lg[r * FPI + 32 + lane];
        float mx = warp_max(fmaxf(l0, l1));
        float k0 = (lane <= r)      ? l0 : -3e38f;
        float k1 = (lane + 32 <= r) ? l1 : -3e38f;
        float mm = warp_max(fmaxf(k0, k1));
        float e0 = __expf(l0 - mx), e1 = __expf(l1 - mx);
        float su = warp_sum(e0 + e1);
        float em0 = (lane <= r)      ? __expf(l0 - mm) : 0.0f;
        float em1 = (lane + 32 <= r) ? __expf(l1 - mm) : 0.0f;
        float ss = warp_sum(em0 + em1);
        float inv = 1.0f / su;
        ph[r * HPI + lane]      = __float2half(e0 * inv);
        ph[r * HPI + 32 + lane] = __float2half(e1 * inv);
        mh[r * HPI + lane]      = __float2half(em0);
        mh[r * HPI + 32 + lane] = __float2half(em1);
        if (lane == 0) {
            g_mloc[(t0 + r) * NH + h] = mm;
            g_sloc[(t0 + r) * NH + h] = ss;
        }
    }
    __syncthreads();

    // P3: ra = P @ V, la = Pm @ V  (warp: rows wm*16.., dims wn*32..)
    float a1[4][4], a2[4][4];
    #pragma unroll
    for (int nt = 0; nt < 4; nt++)
        #pragma unroll
        for (int t = 0; t < 4; t++) { a1[nt][t] = 0.0f; a2[nt][t] = 0.0f; }
    #pragma unroll
    for (int ks = 0; ks < 4; ks++) {
        uint32_t pa[4], ma[4], vb[4][2];
        LDSM4(pa[0], pa[1], pa[2], pa[3],
              smem_u32(&ph[(wm * 16 + a_row) * HPI + ks * 16 + a_kh]));
        LDSM4(ma[0], ma[1], ma[2], ma[3],
              smem_u32(&mh[(wm * 16 + a_row) * HPI + ks * 16 + a_kh]));
        #pragma unroll
        for (int j = 0; j < 2; j++)
            LDSM4T(vb[2*j][0], vb[2*j][1], vb[2*j+1][0], vb[2*j+1][1],
                   smem_u32(&vh[(ks * 16 + (lane & 15)) * HPI
                                + wn * 32 + j * 16 + (lane >> 4) * 8]));
        #pragma unroll
        for (int nt = 0; nt < 4; nt++) {
            MMA16816(a1[nt][0], a1[nt][1], a1[nt][2], a1[nt][3],
                     pa[0], pa[1], pa[2], pa[3], vb[nt][0], vb[nt][1]);
            MMA16816(a2[nt][0], a2[nt][1], a2[nt][2], a2[nt][3],
                     ma[0], ma[1], ma[2], ma[3], vb[nt][0], vb[nt][1]);
        }
    }

    // P4: epilogue (ra fp16, la f32)
    {
        int orow = wm * 16 + (lane >> 2);
        #pragma unroll
        for (int nt = 0; nt < 4; nt++) {
            int col = wn * 32 + nt * 8 + (lane & 3) * 2;
            #pragma unroll
            for (int hh = 0; hh < 2; hh++) {
                int rr = orow + hh * 8;
                size_t base = (size_t)(t0 + rr) * DMODEL + h * DH + col;
                *(__half2*)&g_rah[base] = __floats2half2_rn(a1[nt][hh*2], a1[nt][hh*2+1]);
                *(float2*)&g_la[base] = make_float2(a2[nt][hh*2], a2[nt][hh*2+1]);
            }
        }
    }
}

// ---------------------------------------------------------------------------
// Global attention + merge: one block per (b, l, h). mma.sync everywhere.
// ---------------------------------------------------------------------------
__global__ __launch_bounds__(256, 3) void attn_global_k()
{
    extern __shared__ char smraw[];
    __half* qh = (__half*)smraw;
    __half* kh = (__half*)(smraw + 9216);
    float*  lg = (float*)smraw;
    __half* rh = (__half*)(smraw + 18432);   // ra tile
    __half* ph = (__half*)(smraw + 27648);
    __shared__ float s_cl[64], s_cg[64];

    const __half* gq = g_qkvh;

    int bid = blockIdx.x;
    int h   = bid % NH;
    int l   = (bid / NH) % SEGLEN;
    int b   = bid / (NH * SEGLEN);
    int tid = threadIdx.x;
    const int wid = tid >> 5, lane = tid & 31;
    const int wm = wid >> 1, wn = wid & 1;

    // P0: load q, k2, ra fp16 tiles (rows = segment index)
    for (int i = tid; i < 512; i += 256) {
        int r = i >> 3, c = (i & 7) * 8;
        size_t g = (size_t)(b * SLEN + r * SEGLEN + l) * DMODEL + h * DH + c;
        *(uint4*)&qh[r * HPI + c] = *(const uint4*)&gq[g];
        *(uint4*)&kh[r * HPI + c] = *(const uint4*)&g_k2h[g];
        *(uint4*)&rh[r * HPI + c] = *(const uint4*)&g_rah[g];
    }
    __syncthreads();

    const int a_row = lane & 15, a_kh = (lane >> 4) * 8;
    const int b_row = (lane & 7) + ((lane >> 4) << 3), b_kh = ((lane >> 3) & 1) * 8;

    // P1: logits = Q @ K2^T
    float lc[4][4];
    #pragma unroll
    for (int nt = 0; nt < 4; nt++)
        #pragma unroll
        for (int t = 0; t < 4; t++) lc[nt][t] = 0.0f;
    #pragma unroll
    for (int ks = 0; ks < 4; ks++) {
        uint32_t aa[4], bbf[4][2];
        LDSM4(aa[0], aa[1], aa[2], aa[3],
              smem_u32(&qh[(wm * 16 + a_row) * HPI + ks * 16 + a_kh]));
        #pragma unroll
        for (int j = 0; j < 2; j++)
            LDSM4(bbf[2*j][0], bbf[2*j][1], bbf[2*j+1][0], bbf[2*j+1][1],
                  smem_u32(&kh[(wn * 32 + j * 16 + b_row) * HPI + ks * 16 + b_kh]));
        #pragma unroll
        for (int nt = 0; nt < 4; nt++)
            MMA16816(lc[nt][0], lc[nt][1], lc[nt][2], lc[nt][3],
                     aa[0], aa[1], aa[2], aa[3], bbf[nt][0], bbf[nt][1]);
    }
    __syncthreads();

    // write masked logits f32: mask col >= row
    {
        int crow = wm * 16 + (lane >> 2);
        int ccol = wn * 32 + (lane & 3) * 2;
        #pragma unroll
        for (int nt = 0; nt < 4; nt++) {
            int c0c = ccol + nt * 8;
            lg[crow * FPI + c0c]           = lc[nt][0] + ((c0c     >= crow)     ? NEGINF : 0.0f);
            lg[crow * FPI + c0c + 1]       = lc[nt][1] + ((c0c + 1 >= crow)     ? NEGINF : 0.0f);
            lg[(crow + 8) * FPI + c0c]     = lc[nt][2] + ((c0c     >= crow + 8) ? NEGINF : 0.0f);
            lg[(crow + 8) * FPI + c0c + 1] = lc[nt][3] + ((c0c + 1 >= crow + 8) ? NEGINF : 0.0f);
        }
    }
    __syncthreads();

    // P2: softmax stats + merge coefficients; probs (unnormalized exp) -> ph
    for (int r = wid; r < 64; r += 8) {
        float l0 = lg[r * FPI + lane];
        float l1 = lg[r * FPI + 32 + lane];
        float mg = warp_max(fmaxf(l0, l1));
        float e0 = __expf(l0 - mg), e1 = __expf(l1 - mg);
        float sg = warp_sum(e0 + e1);
        ph[r * HPI + lane]      = __float2half(e0);
        ph[r * HPI + 32 + lane] = __float2half(e1);
        if (lane == 0) {
            int t = b * SLEN + r * SEGLEN + l;
            float mlc = g_mloc[t * NH + h];
            float slc = g_sloc[t * NH + h];
            float m  = fmaxf(mlc, mg);
            float al = __expf(mlc - m);
            float ag = __expf(mg - m);
            float inv = 1.0f / (slc * al + sg * ag);
            s_cl[r] = al * inv;
            s_cg[r] = ag * inv;
        }
    }
    __syncthreads();

    // P3: ga = Pg @ RA
    float ga[4][4];
    #pragma unroll
    for (int nt = 0; nt < 4; nt++)
        #pragma unroll
        for (int t = 0; t < 4; t++) ga[nt][t] = 0.0f;
    #pragma unroll
    for (int ks = 0; ks < 4; ks++) {
        uint32_t pa[4], vb[4][2];
        LDSM4(pa[0], pa[1], pa[2], pa[3],
              smem_u32(&ph[(wm * 16 + a_row) * HPI + ks * 16 + a_kh]));
        #pragma unroll
        for (int j = 0; j < 2; j++)
            LDSM4T(vb[2*j][0], vb[2*j][1], vb[2*j+1][0], vb[2*j+1][1],
                   smem_u32(&rh[(ks * 16 + (lane & 15)) * HPI
                                + wn * 32 + j * 16 + (lane >> 4) * 8]));
        #pragma unroll
        for (int nt = 0; nt < 4; nt++)
            MMA16816(ga[nt][0], ga[nt][1], ga[nt][2], ga[nt][3],
                     pa[0], pa[1], pa[2], pa[3], vb[nt][0], vb[nt][1]);
    }

    // P4: merge with local branch, write fp16 to g_ah
    {
        int orow = wm * 16 + (lane >> 2);
        #pragma unroll
        for (int nt = 0; nt < 4; nt++) {
            int col = wn * 32 + nt * 8 + (lane & 3) * 2;
            #pragma unroll
            for (int hh = 0; hh < 2; hh++) {
                int rr = orow + hh * 8;
                size_t base = (size_t)(b * SLEN + rr * SEGLEN + l) * DMODEL + h * DH + col;
                float2 la = *(const float2*)&g_la[base];
                float cl = s_cl[rr], cg = s_cg[rr];
                float ox = cl * la.x + cg * ga[nt][hh*2];
                float oy = cl * la.y + cg * ga[nt][hh*2+1];
                *(__half2*)&g_ah[base] = __floats2half2_rn(ox, oy);
            }
        }
    }
}

// ---------------------------------------------------------------------------
// LayerNorm: reads kt f32, writes normalized result as fp16
// ---------------------------------------------------------------------------
__global__ __launch_bounds__(256) void ln_k(const float* __restrict__ x,
                                            const float* __restrict__ sc,
                                            const float* __restrict__ bs,
                                            __half* __restrict__ oh)
{
    size_t row = blockIdx.x;
    const float* p = x + row * DMODEL;
    int c = threadIdx.x * 4;
    float4 v = *(const float4*)(p + c);
    float s  = v.x + v.y + v.z + v.w;
    float sq = v.x * v.x + v.y * v.y + v.z * v.z + v.w * v.w;
    s  = warp_sum(s);
    sq = warp_sum(sq);
    __shared__ float rs[8], rq[8];
    int warp = threadIdx.x >> 5, lane = threadIdx.x & 31;
    if (lane == 0) { rs[warp] = s; rq[warp] = sq; }
    __syncthreads();
    if (warp == 0) {
        float a = (lane < 8) ? rs[lane] : 0.0f;
        float b = (lane < 8) ? rq[lane] : 0.0f;
        a = warp_sum(a);
        b = warp_sum(b);
        if (lane == 0) { rs[0] = a; rq[0] = b; }
    }
    __syncthreads();
    float mean = rs[0] * (1.0f / DMODEL);
    float var  = rq[0] * (1.0f / DMODEL) - mean * mean;
    float inv  = rsqrtf(var + 1e-6f);
    float4 g = *(const float4*)(sc + c);
    float4 b4 = *(const float4*)(bs + c);
    v.x = (v.x - mean) * inv * g.x + b4.x;
    v.y = (v.y - mean) * inv * g.y + b4.y;
    v.z = (v.z - mean) * inv * g.z + b4.z;
    v.w = (v.w - mean) * inv * g.w + b4.w;
    size_t o = row * DMODEL + c;
    *(uint2*)(oh + o) = make_uint2(hb(v.x) | (hb(v.y) << 16),
                                   hb(v.z) | (hb(v.w) << 16));
}

// ---------------------------------------------------------------------------
// Host launcher
// ---------------------------------------------------------------------------
extern "C" void kernel_launch(void* const* d_in, const int* in_sizes, int n_in,
                              void* d_out, int out_size)
{
    const float* x    = (const float*)d_in[0];
    const float* Wq   = (const float*)d_in[1];
    const float* Wk   = (const float*)d_in[2];
    const float* Wv   = (const float*)d_in[3];
    const float* Wrow = (const float*)d_in[4];
    const float* lns  = (const float*)d_in[5];
    const float* lnb  = (const float*)d_in[6];
    const float* Wk2  = (const float*)d_in[7];
    const float* Wout = (const float*)d_in[8];
    float* out = (float*)d_out;

    float *kt;
    cudaGetSymbolAddress((void**)&kt, g_kt);

    __half *w16, *ah, *rah, *qkvh, *k2h;
    cudaGetSymbolAddress((void**)&w16,  g_w16);
    cudaGetSymbolAddress((void**)&ah,   g_ah);
    cudaGetSymbolAddress((void**)&rah,  g_rah);
    cudaGetSymbolAddress((void**)&qkvh, g_qkvh);
    cudaGetSymbolAddress((void**)&k2h,  g_k2h);
    const size_t WSZ = (size_t)DMODEL * DMODEL;
    const size_t MSZ = (size_t)NTOK * DMODEL;

    cudaFuncSetAttribute(attn_local_k,  cudaFuncAttributeMaxDynamicSharedMemorySize, ATT_SMEM);
    cudaFuncSetAttribute(attn_global_k, cudaFuncAttributeMaxDynamicSharedMemorySize, ATT_SMEM);
    cudaFuncSetAttribute(gemm_mma<true>,  cudaFuncAttributeMaxDynamicSharedMemorySize, GSMEM);
    cudaFuncSetAttribute(gemm_mma<false>, cudaFuncAttributeMaxDynamicSharedMemorySize, GSMEM);

    // weight prep (transpose + fp16; Wq pre-scaled by 1/sqrt(HD)=0.125)
    dim3 wsg(32, 32), wst(256);
    wprep_k<<<wsg, wst>>>(Wq,   w16 + 0 * WSZ, 0.125f);
    wprep_k<<<wsg, wst>>>(Wk,   w16 + 1 * WSZ, 1.0f);
    wprep_k<<<wsg, wst>>>(Wv,   w16 + 2 * WSZ, 1.0f);
    wprep_k<<<wsg, wst>>>(Wrow, w16 + 3 * WSZ, 1.0f);
    wprep_k<<<wsg, wst>>>(Wk2,  w16 + 4 * WSZ, 1.0f);
    wprep_k<<<wsg, wst>>>(Wout, w16 + 5 * WSZ, 1.0f);

    dim3 gq(3 * DMODEL / 128, NTOK / 128);   // fused QKV: (24, 128)
    dim3 gg(DMODEL / 128, NTOK / 128);       // (8, 128)
    dim3 bt(256);
    const int ACONV_G = (NTOK * DMODEL) / (256 * 4);

    // x -> fp16, then fused QKV projection (fp16 out)
    aconv_k<<<ACONV_G, 256>>>(x, ah);
    gemm_mma<true><<<gq, bt, GSMEM>>>(ah, w16, nullptr, qkvh, MSZ);

    // local attention (tensor-core): writes g_rah fp16, g_la f32, stats
    attn_local_k<<<NBATCH * NSEG * NH, 256, ATT_SMEM>>>();

    // key_row = ra @ Wrow + x (f32) ; LN -> fp16 ; @ Wk2 (fp16 out)
    gemm_mma<false><<<gg, bt, GSMEM>>>(rah, w16 + 3 * WSZ, x, kt, 0);
    ln_k<<<NTOK, 256>>>(kt, lns, lnb, ah);
    gemm_mma<true><<<gg, bt, GSMEM>>>(ah, w16 + 4 * WSZ, nullptr, k2h, 0);

    // global attention + merge (tensor-core): writes merged fp16 into g_ah
    attn_global_k<<<NBATCH * SEGLEN * NH, 256, ATT_SMEM>>>();

    // output projection (f32 out)
    gemm_mma<false><<<gg, bt, GSMEM>>>(ah, w16 + 5 * WSZ, nullptr, out, 0);
}

// round 11
// speedup vs baseline: 4.9250x; 1.0023x over previous
#include <cuda_runtime.h>
#include <cuda_fp16.h>
#include <cstdint>

// ---------------------------------------------------------------------------
// Problem constants
// ---------------------------------------------------------------------------
#define NTOK   16384      // B*S
#define DMODEL 1024
#define NH     16
#define DH     64
#define SEGLEN 64
#define NSEG   64
#define SLEN   4096
#define NBATCH 4
#define NEGINF -1e10f
#define GGRID  296        // persistent GEMM grid (2 per SM on 148 SMs)

// ---------------------------------------------------------------------------
// Scratch (device globals)
// ---------------------------------------------------------------------------
__device__ __half g_qkvh[3 * NTOK * DMODEL];  // q | k | v fp16
__device__ __half g_rah [NTOK * DMODEL];      // row_attn fp16
__device__ __half g_k2h [NTOK * DMODEL];      // key_row2 fp16
__device__ __half g_ah  [NTOK * DMODEL];      // generic fp16 activation
__device__ __half g_lah [NTOK * DMODEL];      // unnormalized masked-local P@V (fp16)
__device__ float  g_kt  [NTOK * DMODEL];      // key_row f32 (pre-LN)
__device__ float  g_mloc[NTOK * NH];
__device__ float  g_sloc[NTOK * NH];

// Pre-transposed fp16 weights: [6][N=1024][K=1024] (Wq pre-scaled by 0.125)
__device__ __half g_w16[6][DMODEL * DMODEL];

// ---------------------------------------------------------------------------
// Helpers
// ---------------------------------------------------------------------------
__device__ __forceinline__ uint32_t smem_u32(const void* p) {
    uint32_t a;
    asm("{ .reg .u64 t; cvta.to.shared.u64 t, %1; cvt.u32.u64 %0, t; }"
        : "=r"(a) : "l"(p));
    return a;
}
__device__ __forceinline__ void cpasync16(uint32_t s, const void* g) {
    asm volatile("cp.async.cg.shared.global [%0], [%1], 16;" :: "r"(s), "l"(g));
}
#define CP_COMMIT() asm volatile("cp.async.commit_group;")
#define CP_WAIT1()  asm volatile("cp.async.wait_group 1;")
#define CP_WAIT0()  asm volatile("cp.async.wait_group 0;")

#define LDSM4(r0, r1, r2, r3, addr) \
    asm volatile("ldmatrix.sync.aligned.m8n8.x4.shared.b16 {%0,%1,%2,%3}, [%4];" \
                 : "=r"(r0), "=r"(r1), "=r"(r2), "=r"(r3) : "r"(addr))
#define LDSM4T(r0, r1, r2, r3, addr) \
    asm volatile("ldmatrix.sync.aligned.m8n8.x4.trans.shared.b16 {%0,%1,%2,%3}, [%4];" \
                 : "=r"(r0), "=r"(r1), "=r"(r2), "=r"(r3) : "r"(addr))

#define MMA16816(c0, c1, c2, c3, a0, a1, a2, a3, b0, b1) \
    asm volatile("mma.sync.aligned.m16n8k16.row.col.f32.f16.f16.f32 " \
                 "{%0,%1,%2,%3}, {%4,%5,%6,%7}, {%8,%9}, {%0,%1,%2,%3};" \
                 : "+f"(c0), "+f"(c1), "+f"(c2), "+f"(c3) \
                 : "r"(a0), "r"(a1), "r"(a2), "r"(a3), "r"(b0), "r"(b1))

__device__ __forceinline__ uint32_t hb(float v) {
    return (uint32_t)__half_as_ushort(__float2half(v));
}

// ---------------------------------------------------------------------------
// Weight transpose + fp16 convert (with scale):  W[K][N] -> T[N][K] fp16
// ---------------------------------------------------------------------------
__global__ __launch_bounds__(256) void wprep_k(const float* __restrict__ W,
                                               __half* __restrict__ T,
                                               float scale)
{
    __shared__ float t[32][33];
    int bn = blockIdx.x * 32;
    int bk = blockIdx.y * 32;
    int x = threadIdx.x & 31;
    int y = threadIdx.x >> 5;
    #pragma unroll
    for (int i = 0; i < 32; i += 8)
        t[y + i][x] = W[(size_t)(bk + y + i) * DMODEL + bn + x];
    __syncthreads();
    #pragma unroll
    for (int i = 0; i < 32; i += 8) {
        float v = t[x][y + i] * scale;
        T[(size_t)(bn + y + i) * DMODEL + bk + x] = __float2half(v);
    }
}

// ---------------------------------------------------------------------------
// Activation fp32 -> fp16 convert (only used for the input x)
// ---------------------------------------------------------------------------
__global__ __launch_bounds__(256) void aconv_k(const float* __restrict__ in,
                                               __half* __restrict__ oh)
{
    size_t i = ((size_t)blockIdx.x * 256 + threadIdx.x) * 4;
    float4 v = *(const float4*)(in + i);
    *(uint2*)(oh + i) = make_uint2(hb(v.x) | (hb(v.y) << 16),
                                   hb(v.z) | (hb(v.w) << 16));
}

// ---------------------------------------------------------------------------
// Persistent tensor-core GEMM (pure fp16, fp32 accumulate).
//   Each CTA loops over tiles t = blockIdx.x + k*gridDim.x.
//   tN = t % tilesX (output column tile / weight select), tM = t / tilesX.
// ---------------------------------------------------------------------------
#define GBK    32
#define GPITCH 40                      // fp16 elements per smem row (80 B)
#define GTILE_B (128 * GPITCH * 2)     // 10240 B per tile
#define GSTAGE_B (2 * GTILE_B)         // A, B = 20480 B
#define GSMEM   (3 * GSTAGE_B)         // 3 stages = 61440 B

template<bool HALF_OUT>
__global__ __launch_bounds__(256) void gemm_mma(
    const __half* __restrict__ Ah,
    const __half* __restrict__ Bf,
    const float* __restrict__ res, void* __restrict__ Cv, size_t matStride,
    int tilesX, int tilesTotal)
{
    extern __shared__ char dsm[];
    const uint32_t sb = smem_u32(dsm);

    const int tid  = threadIdx.x;
    const int wid  = tid >> 5;
    const int lane = tid & 31;
    const int wm = wid & 1;
    const int wn = wid >> 1;
    const int r0 = tid >> 2;
    const int c0 = (tid & 3);
    const int a_row = (lane & 15);
    const int a_kh  = (lane >> 4) * 8;
    const int b_row = (lane & 7) + ((lane >> 4) << 3);
    const int b_kh  = ((lane >> 3) & 1) * 8;

    for (int t = blockIdx.x; t < tilesTotal; t += gridDim.x) {
        const int tN = t % tilesX, tM = t / tilesX;
        const __half* Ahp = Ah + (size_t)(tM * 128) * DMODEL;
        const __half* Bp  = Bf + (size_t)(tN * 128) * DMODEL;

        float acc[4][4][4];
        #pragma unroll
        for (int i = 0; i < 4; i++)
            #pragma unroll
            for (int j = 0; j < 4; j++)
                #pragma unroll
                for (int tt = 0; tt < 4; tt++) acc[i][j][tt] = 0.0f;

        auto issue_chunk = [&](int c, int st) {
            const int k0 = c * GBK;
            uint32_t s = sb + st * GSTAGE_B;
            #pragma unroll
            for (int half = 0; half < 2; half++) {
                int r = r0 + half * 64;
                uint32_t so = (uint32_t)(r * (GPITCH * 2) + c0 * 16);
                size_t go = (size_t)r * DMODEL + (k0 + c0 * 8);
                cpasync16(s + 0 * GTILE_B + so, Ahp + go);
                cpasync16(s + 1 * GTILE_B + so, Bp  + go);
            }
            CP_COMMIT();
        };

        issue_chunk(0, 0);
        issue_chunk(1, 1);

        const int NC = DMODEL / GBK;   // 32
        for (int c = 0; c < NC; c++) {
            const int st = c % 3;
            if (c + 1 < NC) CP_WAIT1(); else CP_WAIT0();
            __syncthreads();
            if (c + 2 < NC) issue_chunk(c + 2, (c + 2) % 3);

            uint32_t sA = sb + st * GSTAGE_B;
            uint32_t sB = sA + GTILE_B;

            #pragma unroll
            for (int ks = 0; ks < 2; ks++) {
                const int kb = ks * 16;
                uint32_t aa[4][4], bbr[4][2];
                #pragma unroll
                for (int mt = 0; mt < 4; mt++) {
                    uint32_t off = (uint32_t)((wm * 64 + mt * 16 + a_row) * (GPITCH * 2)
                                              + (kb + a_kh) * 2);
                    LDSM4(aa[mt][0], aa[mt][1], aa[mt][2], aa[mt][3], sA + off);
                }
                #pragma unroll
                for (int j = 0; j < 2; j++) {
                    uint32_t off = (uint32_t)((wn * 32 + j * 16 + b_row) * (GPITCH * 2)
                                              + (kb + b_kh) * 2);
                    LDSM4(bbr[2*j][0], bbr[2*j][1], bbr[2*j+1][0], bbr[2*j+1][1], sB + off);
                }
                #pragma unroll
                for (int mt = 0; mt < 4; mt++)
                    #pragma unroll
                    for (int nt = 0; nt < 4; nt++)
                        MMA16816(acc[mt][nt][0], acc[mt][nt][1], acc[mt][nt][2], acc[mt][nt][3],
                                 aa[mt][0], aa[mt][1], aa[mt][2], aa[mt][3],
                                 bbr[nt][0], bbr[nt][1]);
            }
        }

        // Epilogue
        const int colb = (tN & 7) * 128;
        #pragma unroll
        for (int mt = 0; mt < 4; mt++) {
            #pragma unroll
            for (int nt = 0; nt < 4; nt++) {
                int row = tM * 128 + wm * 64 + mt * 16 + (lane >> 2);
                int col = colb + wn * 32 + nt * 8 + (lane & 3) * 2;
                #pragma unroll
                for (int hh = 0; hh < 2; hh++) {
                    size_t o = (size_t)(row + hh * 8) * DMODEL + col;
                    float vx = acc[mt][nt][hh * 2 + 0];
                    float vy = acc[mt][nt][hh * 2 + 1];
                    if (HALF_OUT) {
                        __half* Cb = (__half*)Cv + (size_t)(tN >> 3) * matStride;
                        *(__half2*)(Cb + o) = __floats2half2_rn(vx, vy);
                    } else {
                        float* Cb = (float*)Cv + (size_t)(tN >> 3) * matStride;
                        if (res) {
                            float2 rr = *(const float2*)(res + o);
                            vx += rr.x; vy += rr.y;
                        }
                        *(float2*)(Cb + o) = make_float2(vx, vy);
                    }
                }
            }
        }
        __syncthreads();   // guard smem reuse by next tile
    }
}

// ---------------------------------------------------------------------------
// Warp utils
// ---------------------------------------------------------------------------
__device__ __forceinline__ float warp_max(float v) {
    #pragma unroll
    for (int o = 16; o > 0; o >>= 1) v = fmaxf(v, __shfl_xor_sync(0xffffffffu, v, o));
    return v;
}
__device__ __forceinline__ float warp_sum(float v) {
    #pragma unroll
    for (int o = 16; o > 0; o >>= 1) v += __shfl_xor_sync(0xffffffffu, v, o);
    return v;
}

// ---------------------------------------------------------------------------
// Attention smem layout (dynamic, 46080 B)
// ---------------------------------------------------------------------------
#define HPI 72           // half pitch (144 B rows, 16B aligned)
#define FPI 65           // f32 pitch for logits
#define ATT_SMEM 46080

// ---------------------------------------------------------------------------
// Local attention: one block per (b, seg, h). mma.sync everywhere.
// ---------------------------------------------------------------------------
__global__ __launch_bounds__(256, 3) void attn_local_k()
{
    extern __shared__ char smraw[];
    __half* qh = (__half*)smraw;
    __half* kh = (__half*)(smraw + 9216);
    float*  lg = (float*)smraw;
    __half* vh = (__half*)(smraw + 18432);
    __half* ph = (__half*)(smraw + 27648);
    __half* mh = (__half*)(smraw + 36864);

    const __half* gq = g_qkvh;
    const __half* gk = g_qkvh + (size_t)NTOK * DMODEL;
    const __half* gv = g_qkvh + 2 * (size_t)NTOK * DMODEL;

    int bid = blockIdx.x;
    int h   = bid % NH;
    int seg = (bid / NH) % NSEG;
    int b   = bid / (NH * NSEG);
    int t0  = b * SLEN + seg * SEGLEN;
    int tid = threadIdx.x;
    const int wid = tid >> 5, lane = tid & 31;
    const int wm = wid >> 1, wn = wid & 1;

    for (int i = tid; i < 512; i += 256) {
        int r = i >> 3, c = (i & 7) * 8;
        size_t g = (size_t)(t0 + r) * DMODEL + h * DH + c;
        *(uint4*)&qh[r * HPI + c] = *(const uint4*)&gq[g];
        *(uint4*)&kh[r * HPI + c] = *(const uint4*)&gk[g];
        *(uint4*)&vh[r * HPI + c] = *(const uint4*)&gv[g];
    }
    __syncthreads();

    const int a_row = lane & 15, a_kh = (lane >> 4) * 8;
    const int b_row = (lane & 7) + ((lane >> 4) << 3), b_kh = ((lane >> 3) & 1) * 8;

    // P1: logits = Q @ K^T
    float lc[4][4];
    #pragma unroll
    for (int nt = 0; nt < 4; nt++)
        #pragma unroll
        for (int t = 0; t < 4; t++) lc[nt][t] = 0.0f;
    #pragma unroll
    for (int ks = 0; ks < 4; ks++) {
        uint32_t aa[4], bbf[4][2];
        LDSM4(aa[0], aa[1], aa[2], aa[3],
              smem_u32(&qh[(wm * 16 + a_row) * HPI + ks * 16 + a_kh]));
        #pragma unroll
        for (int j = 0; j < 2; j++)
            LDSM4(bbf[2*j][0], bbf[2*j][1], bbf[2*j+1][0], bbf[2*j+1][1],
                  smem_u32(&kh[(wn * 32 + j * 16 + b_row) * HPI + ks * 16 + b_kh]));
        #pragma unroll
        for (int nt = 0; nt < 4; nt++)
            MMA16816(lc[nt][0], lc[nt][1], lc[nt][2], lc[nt][3],
                     aa[0], aa[1], aa[2], aa[3], bbf[nt][0], bbf[nt][1]);
    }
    __syncthreads();

    {
        int crow = wm * 16 + (lane >> 2);
        int ccol = wn * 32 + (lane & 3) * 2;
        #pragma unroll
        for (int nt = 0; nt < 4; nt++) {
            lg[crow * FPI + ccol + nt * 8]           = lc[nt][0];
            lg[crow * FPI + ccol + nt * 8 + 1]       = lc[nt][1];
            lg[(crow + 8) * FPI + ccol + nt * 8]     = lc[nt][2];
            lg[(crow + 8) * FPI + ccol + nt * 8 + 1] = lc[nt][3];
        }
    }
    __syncthreads();

    // P2: dual softmax
    for (int r = wid; r < 64; r += 8) {
        float l0 = lg[r * FPI + lane];
        float l1 = lg[r * FPI + 32 + lane];
        float mx = warp_max(fmaxf(l0, l1));
        float k0 = (lane <= r)      ? l0 : -3e38f;
        float k1 = (lane + 32 <= r) ? l1 : -3e38f;
        float mm = warp_max(fmaxf(k0, k1));
        float e0 = __expf(l0 - mx), e1 = __expf(l1 - mx);
        float su = warp_sum(e0 + e1);
        float em0 = (lane <= r)      ? __expf(l0 - mm) : 0.0f;
        float em1 = (lane + 32 <= r) ? __expf(l1 - mm) : 0.0f;
        float ss = warp_sum(em0 + em1);
        float inv = 1.0f / su;
        ph[r * HPI + lane]      = __float2half(e0 * inv);
        ph[r * HPI + 32 + lane] = __float2half(e1 * inv);
        mh[r * HPI + lane]      = __float2half(em0);
        mh[r * HPI + 32 + lane] = __float2half(em1);
        if (lane == 0) {
            g_mloc[(t0 + r) * NH + h] = mm;
            g_sloc[(t0 + r) * NH + h] = ss;
        }
    }
    __syncthreads();

    // P3: ra = P @ V, la = Pm @ V
    float a1[4][4], a2[4][4];
    #pragma unroll
    for (int nt = 0; nt < 4; nt++)
        #pragma unroll
        for (int t = 0; t < 4; t++) { a1[nt][t] = 0.0f; a2[nt][t] = 0.0f; }
    #pragma unroll
    for (int ks = 0; ks < 4; ks++) {
        uint32_t pa[4], ma[4], vb[4][2];
        LDSM4(pa[0], pa[1], pa[2], pa[3],
              smem_u32(&ph[(wm * 16 + a_row) * HPI + ks * 16 + a_kh]));
        LDSM4(ma[0], ma[1], ma[2], ma[3],
              smem_u32(&mh[(wm * 16 + a_row) * HPI + ks * 16 + a_kh]));
        #pragma unroll
        for (int j = 0; j < 2; j++)
            LDSM4T(vb[2*j][0], vb[2*j][1], vb[2*j+1][0], vb[2*j+1][1],
                   smem_u32(&vh[(ks * 16 + (lane & 15)) * HPI
                                + wn * 32 + j * 16 + (lane >> 4) * 8]));
        #pragma unroll
        for (int nt = 0; nt < 4; nt++) {
            MMA16816(a1[nt][0], a1[nt][1], a1[nt][2], a1[nt][3],
                     pa[0], pa[1], pa[2], pa[3], vb[nt][0], vb[nt][1]);
            MMA16816(a2[nt][0], a2[nt][1], a2[nt][2], a2[nt][3],
                     ma[0], ma[1], ma[2], ma[3], vb[nt][0], vb[nt][1]);
        }
    }

    // P4: epilogue (ra fp16, la fp16)
    {
        int orow = wm * 16 + (lane >> 2);
        #pragma unroll
        for (int nt = 0; nt < 4; nt++) {
            int col = wn * 32 + nt * 8 + (lane & 3) * 2;
            #pragma unroll
            for (int hh = 0; hh < 2; hh++) {
                int rr = orow + hh * 8;
                size_t base = (size_t)(t0 + rr) * DMODEL + h * DH + col;
                *(__half2*)&g_rah[base] = __floats2half2_rn(a1[nt][hh*2], a1[nt][hh*2+1]);
                *(__half2*)&g_lah[base] = __floats2half2_rn(a2[nt][hh*2], a2[nt][hh*2+1]);
            }
        }
    }
}

// ---------------------------------------------------------------------------
// Global attention + merge: one block per (b, l, h). mma.sync everywhere.
// ---------------------------------------------------------------------------
__global__ __launch_bounds__(256, 3) void attn_global_k()
{
    extern __shared__ char smraw[];
    __half* qh = (__half*)smraw;
    __half* kh = (__half*)(smraw + 9216);
    float*  lg = (float*)smraw;
    __half* rh = (__half*)(smraw + 18432);
    __half* ph = (__half*)(smraw + 27648);
    __shared__ float s_cl[64], s_cg[64];

    const __half* gq = g_qkvh;

    int bid = blockIdx.x;
    int h   = bid % NH;
    int l   = (bid / NH) % SEGLEN;
    int b   = bid / (NH * SEGLEN);
    int tid = threadIdx.x;
    const int wid = tid >> 5, lane = tid & 31;
    const int wm = wid >> 1, wn = wid & 1;

    for (int i = tid; i < 512; i += 256) {
        int r = i >> 3, c = (i & 7) * 8;
        size_t g = (size_t)(b * SLEN + r * SEGLEN + l) * DMODEL + h * DH + c;
        *(uint4*)&qh[r * HPI + c] = *(const uint4*)&gq[g];
        *(uint4*)&kh[r * HPI + c] = *(const uint4*)&g_k2h[g];
        *(uint4*)&rh[r * HPI + c] = *(const uint4*)&g_rah[g];
    }
    __syncthreads();

    const int a_row = lane & 15, a_kh = (lane >> 4) * 8;
    const int b_row = (lane & 7) + ((lane >> 4) << 3), b_kh = ((lane >> 3) & 1) * 8;

    // P1: logits = Q @ K2^T
    float lc[4][4];
    #pragma unroll
    for (int nt = 0; nt < 4; nt++)
        #pragma unroll
        for (int t = 0; t < 4; t++) lc[nt][t] = 0.0f;
    #pragma unroll
    for (int ks = 0; ks < 4; ks++) {
        uint32_t aa[4], bbf[4][2];
        LDSM4(aa[0], aa[1], aa[2], aa[3],
              smem_u32(&qh[(wm * 16 + a_row) * HPI + ks * 16 + a_kh]));
        #pragma unroll
        for (int j = 0; j < 2; j++)
            LDSM4(bbf[2*j][0], bbf[2*j][1], bbf[2*j+1][0], bbf[2*j+1][1],
                  smem_u32(&kh[(wn * 32 + j * 16 + b_row) * HPI + ks * 16 + b_kh]));
        #pragma unroll
        for (int nt = 0; nt < 4; nt++)
            MMA16816(lc[nt][0], lc[nt][1], lc[nt][2], lc[nt][3],
                     aa[0], aa[1], aa[2], aa[3], bbf[nt][0], bbf[nt][1]);
    }
    __syncthreads();

    {
        int crow = wm * 16 + (lane >> 2);
        int ccol = wn * 32 + (lane & 3) * 2;
        #pragma unroll
        for (int nt = 0; nt < 4; nt++) {
            int c0c = ccol + nt * 8;
            lg[crow * FPI + c0c]           = lc[nt][0] + ((c0c     >= crow)     ? NEGINF : 0.0f);
            lg[crow * FPI + c0c + 1]       = lc[nt][1] + ((c0c + 1 >= crow)     ? NEGINF : 0.0f);
            lg[(crow + 8) * FPI + c0c]     = lc[nt][2] + ((c0c     >= crow + 8) ? NEGINF : 0.0f);
            lg[(crow + 8) * FPI + c0c + 1] = lc[nt][3] + ((c0c + 1 >= crow + 8) ? NEGINF : 0.0f);
        }
    }
    __syncthreads();

    // P2: softmax stats + merge coefficients
    for (int r = wid; r < 64; r += 8) {
        float l0 = lg[r * FPI + lane];
        float l1 = lg[r * FPI + 32 + lane];
        float mg = warp_max(fmaxf(l0, l1));
        float e0 = __expf(l0 - mg), e1 = __expf(l1 - mg);
        float sg = warp_sum(e0 + e1);
        ph[r * HPI + lane]      = __float2half(e0);
        ph[r * HPI + 32 + lane] = __float2half(e1);
        if (lane == 0) {
            int t = b * SLEN + r * SEGLEN + l;
            float mlc = g_mloc[t * NH + h];
            float slc = g_sloc[t * NH + h];
            float m  = fmaxf(mlc, mg);
            float al = __expf(mlc - m);
            float ag = __expf(mg - m);
            float inv = 1.0f / (slc * al + sg * ag);
            s_cl[r] = al * inv;
            s_cg[r] = ag * inv;
        }
    }
    __syncthreads();

    // P3: ga = Pg @ RA
    float ga[4][4];
    #pragma unroll
    for (int nt = 0; nt < 4; nt++)
        #pragma unroll
        for (int t = 0; t < 4; t++) ga[nt][t] = 0.0f;
    #pragma unroll
    for (int ks = 0; ks < 4; ks++) {
        uint32_t pa[4], vb[4][2];
        LDSM4(pa[0], pa[1], pa[2], pa[3],
              smem_u32(&ph[(wm * 16 + a_row) * HPI + ks * 16 + a_kh]));
        #pragma unroll
        for (int j = 0; j < 2; j++)
            LDSM4T(vb[2*j][0], vb[2*j][1], vb[2*j+1][0], vb[2*j+1][1],
                   smem_u32(&rh[(ks * 16 + (lane & 15)) * HPI
                                + wn * 32 + j * 16 + (lane >> 4) * 8]));
        #pragma unroll
        for (int nt = 0; nt < 4; nt++)
            MMA16816(ga[nt][0], ga[nt][1], ga[nt][2], ga[nt][3],
                     pa[0], pa[1], pa[2], pa[3], vb[nt][0], vb[nt][1]);
    }

    // P4: merge with local branch
    {
        int orow = wm * 16 + (lane >> 2);
        #pragma unroll
        for (int nt = 0; nt < 4; nt++) {
            int col = wn * 32 + nt * 8 + (lane & 3) * 2;
            #pragma unroll
            for (int hh = 0; hh < 2; hh++) {
                int rr = orow + hh * 8;
                size_t base = (size_t)(b * SLEN + rr * SEGLEN + l) * DMODEL + h * DH + col;
                float2 la = __half22float2(*(__half2*)&g_lah[base]);
                float cl = s_cl[rr], cg = s_cg[rr];
                float ox = cl * la.x + cg * ga[nt][hh*2];
                float oy = cl * la.y + cg * ga[nt][hh*2+1];
                *(__half2*)&g_ah[base] = __floats2half2_rn(ox, oy);
            }
        }
    }
}

// ---------------------------------------------------------------------------
// LayerNorm: reads kt f32, writes normalized result as fp16
// ---------------------------------------------------------------------------
__global__ __launch_bounds__(256) void ln_k(const float* __restrict__ x,
                                            const float* __restrict__ sc,
                                            const float* __restrict__ bs,
                                            __half* __restrict__ oh)
{
    size_t row = blockIdx.x;
    const float* p = x + row * DMODEL;
    int c = threadIdx.x * 4;
    float4 v = *(const float4*)(p + c);
    float s  = v.x + v.y + v.z + v.w;
    float sq = v.x * v.x + v.y * v.y + v.z * v.z + v.w * v.w;
    s  = warp_sum(s);
    sq = warp_sum(sq);
    __shared__ float rs[8], rq[8];
    int warp = threadIdx.x >> 5, lane = threadIdx.x & 31;
    if (lane == 0) { rs[warp] = s; rq[warp] = sq; }
    __syncthreads();
    if (warp == 0) {
        float a = (lane < 8) ? rs[lane] : 0.0f;
        float b = (lane < 8) ? rq[lane] : 0.0f;
        a = warp_sum(a);
        b = warp_sum(b);
        if (lane == 0) { rs[0] = a; rq[0] = b; }
    }
    __syncthreads();
    float mean = rs[0] * (1.0f / DMODEL);
    float var  = rq[0] * (1.0f / DMODEL) - mean * mean;
    float inv  = rsqrtf(var + 1e-6f);
    float4 g = *(const float4*)(sc + c);
    float4 b4 = *(const float4*)(bs + c);
    v.x = (v.x - mean) * inv * g.x + b4.x;
    v.y = (v.y - mean) * inv * g.y + b4.y;
    v.z = (v.z - mean) * inv * g.z + b4.z;
    v.w = (v.w - mean) * inv * g.w + b4.w;
    size_t o = row * DMODEL + c;
    *(uint2*)(oh + o) = make_uint2(hb(v.x) | (hb(v.y) << 16),
                                   hb(v.z) | (hb(v.w) << 16));
}

// ---------------------------------------------------------------------------
// Host launcher
// ---------------------------------------------------------------------------
extern "C" void kernel_launch(void* const* d_in, const int* in_sizes, int n_in,
                              void* d_out, int out_size)
{
    const float* x    = (const float*)d_in[0];
    const float* Wq   = (const float*)d_in[1];
    const float* Wk   = (const float*)d_in[2];
    const float* Wv   = (const float*)d_in[3];
    const float* Wrow = (const float*)d_in[4];
    const float* lns  = (const float*)d_in[5];
    const float* lnb  = (const float*)d_in[6];
    const float* Wk2  = (const float*)d_in[7];
    const float* Wout = (const float*)d_in[8];
    float* out = (float*)d_out;

    float *kt;
    cudaGetSymbolAddress((void**)&kt, g_kt);

    __half *w16, *ah, *rah, *qkvh, *k2h;
    cudaGetSymbolAddress((void**)&w16,  g_w16);
    cudaGetSymbolAddress((void**)&ah,   g_ah);
    cudaGetSymbolAddress((void**)&rah,  g_rah);
    cudaGetSymbolAddress((void**)&qkvh, g_qkvh);
    cudaGetSymbolAddress((void**)&k2h,  g_k2h);
    const size_t MSZ = (size_t)NTOK * DMODEL;
    const size_t WSZ = (size_t)DMODEL * DMODEL;

    cudaFuncSetAttribute(attn_local_k,  cudaFuncAttributeMaxDynamicSharedMemorySize, ATT_SMEM);
    cudaFuncSetAttribute(attn_global_k, cudaFuncAttributeMaxDynamicSharedMemorySize, ATT_SMEM);
    cudaFuncSetAttribute(gemm_mma<true>,  cudaFuncAttributeMaxDynamicSharedMemorySize, GSMEM);
    cudaFuncSetAttribute(gemm_mma<false>, cudaFuncAttributeMaxDynamicSharedMemorySize, GSMEM);

    // weight prep (transpose + fp16; Wq pre-scaled by 1/sqrt(HD)=0.125)
    dim3 wsg(32, 32), wst(256);
    wprep_k<<<wsg, wst>>>(Wq,   w16 + 0 * WSZ, 0.125f);
    wprep_k<<<wsg, wst>>>(Wk,   w16 + 1 * WSZ, 1.0f);
    wprep_k<<<wsg, wst>>>(Wv,   w16 + 2 * WSZ, 1.0f);
    wprep_k<<<wsg, wst>>>(Wrow, w16 + 3 * WSZ, 1.0f);
    wprep_k<<<wsg, wst>>>(Wk2,  w16 + 4 * WSZ, 1.0f);
    wprep_k<<<wsg, wst>>>(Wout, w16 + 5 * WSZ, 1.0f);

    dim3 bt(256);
    const int ACONV_G = (NTOK * DMODEL) / (256 * 4);

    // x -> fp16, then fused QKV projection (fp16 out), persistent grid
    aconv_k<<<ACONV_G, 256>>>(x, ah);
    gemm_mma<true><<<GGRID, bt, GSMEM>>>(ah, w16, nullptr, qkvh, MSZ, 24, 3072);

    // local attention (tensor-core)
    attn_local_k<<<NBATCH * NSEG * NH, 256, ATT_SMEM>>>();

    // key_row = ra @ Wrow + x (f32) ; LN -> fp16 ; @ Wk2 (fp16 out)
    gemm_mma<false><<<GGRID, bt, GSMEM>>>(rah, w16 + 3 * WSZ, x, kt, 0, 8, 1024);
    ln_k<<<NTOK, 256>>>(kt, lns, lnb, ah);
    gemm_mma<true><<<GGRID, bt, GSMEM>>>(ah, w16 + 4 * WSZ, nullptr, k2h, 0, 8, 1024);

    // global attention + merge (tensor-core)
    attn_global_k<<<NBATCH * SEGLEN * NH, 256, ATT_SMEM>>>();

    // output projection (f32 out)
    gemm_mma<false><<<GGRID, bt, GSMEM>>>(ah, w16 + 5 * WSZ, nullptr, out, 0, 8, 1024);
}